// round 9
// baseline (speedup 1.0000x reference)
#include <cuda_runtime.h>
#include <cuda_bf16.h>
#include <cstdint>
#include <math.h>

// Problem constants
#define NN 50000
#define EG 800000

// ---------------- scratch (device globals; no runtime allocation) ----------
__device__ float  g_Q   [(size_t)NN * 128];
__device__ float  g_K   [(size_t)NN * 128];
__device__ float  g_V   [(size_t)NN * 128];
__device__ float  g_h1  [(size_t)NN * 128];
__device__ float  g_hidh[(size_t)NN * 256];
__device__ float  g_wV  [(size_t)NN * 128];
__device__ float  g_z   [(size_t)NN * 8];
__device__ float  g_EA  [(size_t)EG * 128];
__device__ float  g_e1  [(size_t)EG * 128];
__device__ float  g_hide[(size_t)EG * 256];
__device__ double g_sum [4 * 128];
__device__ double g_sq  [4 * 128];
__device__ float  g_bnsc[4 * 128];
__device__ float  g_bnsh[4 * 128];

// pre-split weights: hi plane [0, TOTW), lo plane [TOTW, 2*TOTW), bf16
#define OFF_WQ   0
#define OFF_WK   16384
#define OFF_WV   32768
#define OFF_WE   49152
#define OFF_WOH  65536
#define OFF_WOE  81920
#define OFF_WH1  98304
#define OFF_WE1  131072
#define OFF_WH2  163840
#define OFF_WE2  196608
#define TOTW     229376
__device__ __nv_bfloat16 g_Wb[2 * TOTW];

// ---------------- zero accumulators ----------------------------------------
__global__ void k_zero() {
    size_t i = (size_t)blockIdx.x * blockDim.x + threadIdx.x;
    size_t stride = (size_t)gridDim.x * blockDim.x;
    for (size_t j = i; j < (size_t)NN * 128; j += stride) g_wV[j] = 0.f;
    for (size_t j = i; j < (size_t)NN * 8;   j += stride) g_z[j]  = 0.f;
    if (i < 512) { g_sum[i] = 0.0; g_sq[i] = 0.0; }
}

// ============================================================================
// helpers
// ============================================================================
__device__ __forceinline__ uint32_t smem_u32(const void* p) {
    uint32_t a;
    asm("{ .reg .u64 t; cvta.to.shared.u64 t, %1; cvt.u32.u64 %0, t; }"
        : "=r"(a) : "l"(p));
    return a;
}

__device__ __forceinline__ void ldsm_x4(uint32_t addr, uint32_t* r) {
    asm volatile("ldmatrix.sync.aligned.m8n8.x4.shared.b16 {%0,%1,%2,%3}, [%4];"
        : "=r"(r[0]), "=r"(r[1]), "=r"(r[2]), "=r"(r[3]) : "r"(addr));
}

__device__ __forceinline__ void mma_bf16(float* acc, const uint32_t* a, const uint32_t* b) {
    asm volatile(
        "mma.sync.aligned.m16n8k16.row.col.f32.bf16.bf16.f32 "
        "{%0,%1,%2,%3},{%4,%5,%6,%7},{%8,%9},{%0,%1,%2,%3};"
        : "+f"(acc[0]), "+f"(acc[1]), "+f"(acc[2]), "+f"(acc[3])
        : "r"(a[0]), "r"(a[1]), "r"(a[2]), "r"(a[3]), "r"(b[0]), "r"(b[1]));
}

__device__ __forceinline__ void split_pair(float x0, float x1, uint32_t& hi, uint32_t& lo)
{
    __nv_bfloat162 h = __floats2bfloat162_rn(x0, x1);
    float r0 = x0 - __bfloat162float(__low2bfloat16(h));
    float r1 = x1 - __bfloat162float(__high2bfloat16(h));
    __nv_bfloat162 l = __floats2bfloat162_rn(r0, r1);
    hi = *reinterpret_cast<uint32_t*>(&h);
    lo = *reinterpret_cast<uint32_t*>(&l);
}

// ============================================================================
// Weight pre-split
// ============================================================================
__global__ __launch_bounds__(256)
void k_wsplit(const float* __restrict__ WQ,  const float* __restrict__ WK,
              const float* __restrict__ WV,  const float* __restrict__ WE,
              const float* __restrict__ WOh, const float* __restrict__ WOe,
              const float* __restrict__ Wh1, const float* __restrict__ We1,
              const float* __restrict__ Wh2, const float* __restrict__ We2)
{
    int p = blockIdx.x * 256 + threadIdx.x;
    if (p >= TOTW / 2) return;
    const float* W;
    int Kd, Nd, local, base;
    if (p < 49152) {
        int m = p >> 13;
        local = p & 8191;
        Kd = 128; Nd = 128; base = m << 14;
        W = (m == 0) ? WQ : (m == 1) ? WK : (m == 2) ? WV :
            (m == 3) ? WE : (m == 4) ? WOh : WOe;
    } else if (p < 65536)  { local = p - 49152; Kd = 128; Nd = 256; base = OFF_WH1; W = Wh1; }
    else if (p < 81920)    { local = p - 65536; Kd = 128; Nd = 256; base = OFF_WE1; W = We1; }
    else if (p < 98304)    { local = p - 81920; Kd = 256; Nd = 128; base = OFF_WH2; W = Wh2; }
    else                   { local = p - 98304; Kd = 256; Nd = 128; base = OFF_WE2; W = We2; }
    int n  = local % Nd;
    int k  = (local / Nd) * 2;
    float x0 = W[(size_t)k * Nd + n];
    float x1 = W[(size_t)(k + 1) * Nd + n];
    uint32_t hi, lo;
    split_pair(x0, x1, hi, lo);
    size_t o = (size_t)base + (size_t)n * Kd + k;
    *(uint32_t*)((char*)g_Wb + o * 2)          = hi;
    *(uint32_t*)((char*)g_Wb + (o + TOTW) * 2) = lo;
}

// ============================================================================
// Shared GEMM mainloop macro pieces are inlined in both kernels below.
// Pipelined HMMA bf16 3-split GEMM. K = KC*32, N-tile = 128.
// ============================================================================
#define A_CH_B 10240
#define A_BUF_B 20480
#define B_BASE 40960

template<int KC>
__global__ __launch_bounds__(256, (KC == 4) ? 2 : 1)
void k_mmgemm(const float* __restrict__ A, int Ald,
              const __nv_bfloat16* __restrict__ Whi,
              const __nv_bfloat16* __restrict__ Wlo,
              const float* __restrict__ bias, const float* __restrict__ res,
              float* __restrict__ C, int Cld, int M, int relu,
              const float* __restrict__ Asc, const float* __restrict__ Ash,
              const float* __restrict__ Zrow,
              const float* __restrict__ Rsc, const float* __restrict__ Rsh,
              double* sumP, double* sqP)
{
    extern __shared__ char smem[];
    constexpr int K  = KC * 32;
    constexpr int BS = K + 8;
    constexpr int KSH = (KC == 4) ? 4 : 5;
    constexpr uint32_t BBs = 128u * BS * 2u;
    const uint32_t sbase = smem_u32(smem);

    const int tid  = threadIdx.x;
    const int lane = tid & 31;
    const int wid  = tid >> 5;
    const int wm   = wid >> 2;
    const int wn   = wid & 3;

    for (int i = tid; i < 128 * (K >> 3); i += 256) {
        int k8 = i & ((K >> 3) - 1);
        int n  = i >> KSH;
        uint4 vh = *(const uint4*)(Whi + (size_t)n * K + (k8 << 3));
        uint4 vl = *(const uint4*)(Wlo + (size_t)n * K + (k8 << 3));
        uint32_t off = ((uint32_t)n * BS + (k8 << 3)) * 2u;
        *(uint4*)(smem + B_BASE + off)       = vh;
        *(uint4*)(smem + B_BASE + BBs + off) = vl;
    }

    const int tiles = (M + 127) >> 7;
    const int a_row = (lane & 15);
    const int a_k   = (lane >> 4) << 3;
    const int b_row = (lane & 7) + ((lane >> 4) << 3);
    const int b_k   = ((lane >> 3) & 1) << 3;

    float4 pf[4];
    int t = blockIdx.x;
    if (t < tiles) {
        int m0 = t << 7;
        #pragma unroll
        for (int j = 0; j < 4; j++) {
            int idx = tid + (j << 8);
            int gm = m0 + (idx >> 3); if (gm > M - 1) gm = M - 1;
            pf[j] = *(const float4*)(A + (size_t)gm * Ald + ((idx & 7) << 2));
        }
    }
    int buf = 0;

    for (; t < tiles; t += gridDim.x) {
        const int m0 = t << 7;
        float acc[4][4][4] = {};
        for (int kc = 0; kc < KC; kc++) {
            const int kb = kc << 5;
            {
                char* ah_base = smem + buf * A_BUF_B;
                #pragma unroll
                for (int j = 0; j < 4; j++) {
                    int idx = tid + (j << 8);
                    int row = idx >> 3;
                    int c4  = (idx & 7) << 2;
                    float4 v = pf[j];
                    if (Asc) {
                        float4 sc = *(const float4*)(Asc + kb + c4);
                        float4 sh = *(const float4*)(Ash + kb + c4);
                        v.x = v.x * sc.x + sh.x;
                        v.y = v.y * sc.y + sh.y;
                        v.z = v.z * sc.z + sh.z;
                        v.w = v.w * sc.w + sh.w;
                    }
                    if (Zrow) {
                        int gm = m0 + row; if (gm > M - 1) gm = M - 1;
                        float zz = 1.0f / (Zrow[(size_t)gm * 8 + ((kb + c4) >> 4)] + 1e-6f);
                        v.x *= zz; v.y *= zz; v.z *= zz; v.w *= zz;
                    }
                    uint32_t h01, l01, h23, l23;
                    split_pair(v.x, v.y, h01, l01);
                    split_pair(v.z, v.w, h23, l23);
                    uint32_t off = ((uint32_t)row * 40 + c4) * 2u;
                    *(uint2*)(ah_base + off)          = make_uint2(h01, h23);
                    *(uint2*)(ah_base + A_CH_B + off) = make_uint2(l01, l23);
                }
            }
            __syncthreads();
            {
                int kc2 = kc + 1, tn = t;
                if (kc2 == KC) { kc2 = 0; tn = t + gridDim.x; }
                if (tn < tiles) {
                    int m2 = tn << 7, kb2 = kc2 << 5;
                    #pragma unroll
                    for (int j = 0; j < 4; j++) {
                        int idx = tid + (j << 8);
                        int gm = m2 + (idx >> 3); if (gm > M - 1) gm = M - 1;
                        pf[j] = *(const float4*)(A + (size_t)gm * Ald + kb2 + ((idx & 7) << 2));
                    }
                }
            }
            const uint32_t abase = sbase + buf * A_BUF_B;
            #pragma unroll
            for (int ks = 0; ks < 2; ks++) {
                const int ka = ks << 4;
                uint32_t bh[4][2], bl[4][2];
                #pragma unroll
                for (int np = 0; np < 2; np++) {
                    uint32_t roff = ((uint32_t)(wn * 32 + np * 16 + b_row) * BS
                                     + kb + ka + b_k) * 2u;
                    uint32_t rh[4], rl[4];
                    ldsm_x4(sbase + B_BASE + roff, rh);
                    ldsm_x4(sbase + B_BASE + BBs + roff, rl);
                    bh[np*2][0] = rh[0]; bh[np*2][1] = rh[1];
                    bh[np*2+1][0] = rh[2]; bh[np*2+1][1] = rh[3];
                    bl[np*2][0] = rl[0]; bl[np*2][1] = rl[1];
                    bl[np*2+1][0] = rl[2]; bl[np*2+1][1] = rl[3];
                }
                uint32_t ah[4][4], al[4][4];
                #pragma unroll
                for (int mt = 0; mt < 4; mt++) {
                    uint32_t roff = ((uint32_t)(wm * 64 + mt * 16 + a_row) * 40
                                     + ka + a_k) * 2u;
                    ldsm_x4(abase + roff, ah[mt]);
                    ldsm_x4(abase + A_CH_B + roff, al[mt]);
                }
                #pragma unroll
                for (int mt = 0; mt < 4; mt++)
                    #pragma unroll
                    for (int nt = 0; nt < 4; nt++) {
                        mma_bf16(acc[mt][nt], ah[mt], bh[nt]);
                        mma_bf16(acc[mt][nt], ah[mt], bl[nt]);
                        mma_bf16(acc[mt][nt], al[mt], bh[nt]);
                    }
            }
            buf ^= 1;
        }

        const int g  = lane >> 2;
        const int t2 = (lane & 3) << 1;
        #pragma unroll
        for (int nt = 0; nt < 4; nt++) {
            int c0 = wn * 32 + nt * 8 + t2;
            float2 bv = *(const float2*)(bias + c0);
            float2 rs = make_float2(1.f, 1.f), rb = make_float2(0.f, 0.f);
            if (Rsc) {
                rs = *(const float2*)(Rsc + c0);
                rb = *(const float2*)(Rsh + c0);
            }
            float ps0 = 0.f, ps1 = 0.f, q0 = 0.f, q1 = 0.f;
            #pragma unroll
            for (int mt = 0; mt < 4; mt++) {
                #pragma unroll
                for (int half = 0; half < 2; half++) {
                    int r = m0 + wm * 64 + mt * 16 + g + half * 8;
                    float2 v = make_float2(acc[mt][nt][half*2]   + bv.x,
                                           acc[mt][nt][half*2+1] + bv.y);
                    if (r < M) {
                        size_t o = (size_t)r * Cld + c0;
                        if (res) {
                            float2 rv = *(const float2*)(res + o);
                            v.x += rv.x * rs.x + rb.x;
                            v.y += rv.y * rs.y + rb.y;
                        }
                        if (relu) { v.x = fmaxf(v.x, 0.f); v.y = fmaxf(v.y, 0.f); }
                        *(float2*)(C + o) = v;
                    } else { v.x = 0.f; v.y = 0.f; }
                    ps0 += v.x; q0 += v.x * v.x;
                    ps1 += v.y; q1 += v.y * v.y;
                }
            }
            if (sumP) {
                #pragma unroll
                for (int off = 16; off >= 4; off >>= 1) {
                    ps0 += __shfl_down_sync(0xffffffffu, ps0, off);
                    ps1 += __shfl_down_sync(0xffffffffu, ps1, off);
                    q0  += __shfl_down_sync(0xffffffffu, q0,  off);
                    q1  += __shfl_down_sync(0xffffffffu, q1,  off);
                }
                if (lane < 4) {
                    int cc = wn * 32 + nt * 8 + lane * 2;
                    atomicAdd(&sumP[cc],     (double)ps0);
                    atomicAdd(&sumP[cc + 1], (double)ps1);
                    atomicAdd(&sqP[cc],      (double)q0);
                    atomicAdd(&sqP[cc + 1],  (double)q1);
                }
            }
        }
    }
}

// ============================================================================
// Fused E-projection + edge attention: per tile of 128 edges,
//   Ee = e @ WE + bE (HMMA 3-split), then in epilogue:
//   score = K[src]*Q[dst]*0.25*Ee  -> written to g_EA (= e_attn)
//   s = exp(clip(head-sum))        -> atomics into g_wV (V[src]*s) and g_z
// Each epilogue quad (4 lanes, same g) owns one row (edge) and heads
// {2wn, 2wn+1}; head-sum = 2x shfl_xor within quad.
// ============================================================================
__global__ __launch_bounds__(256, 2)
void k_eproj(const float* __restrict__ A,
             const __nv_bfloat16* __restrict__ Whi,
             const __nv_bfloat16* __restrict__ Wlo,
             const float* __restrict__ bias,
             const int* __restrict__ src, const int* __restrict__ dst,
             int M)
{
    extern __shared__ char smem[];
    constexpr int BS = 136;
    constexpr uint32_t BBs = 128u * BS * 2u;
    const uint32_t sbase = smem_u32(smem);

    const int tid  = threadIdx.x;
    const int lane = tid & 31;
    const int wid  = tid >> 5;
    const int wm   = wid >> 2;
    const int wn   = wid & 3;

    for (int i = tid; i < 128 * 16; i += 256) {
        int k8 = i & 15;
        int n  = i >> 4;
        uint4 vh = *(const uint4*)(Whi + (size_t)n * 128 + (k8 << 3));
        uint4 vl = *(const uint4*)(Wlo + (size_t)n * 128 + (k8 << 3));
        uint32_t off = ((uint32_t)n * BS + (k8 << 3)) * 2u;
        *(uint4*)(smem + B_BASE + off)       = vh;
        *(uint4*)(smem + B_BASE + BBs + off) = vl;
    }

    const int tiles = (M + 127) >> 7;
    const int a_row = (lane & 15);
    const int a_k   = (lane >> 4) << 3;
    const int b_row = (lane & 7) + ((lane >> 4) << 3);
    const int b_k   = ((lane >> 3) & 1) << 3;

    float4 pf[4];
    int t = blockIdx.x;
    if (t < tiles) {
        int m0 = t << 7;
        #pragma unroll
        for (int j = 0; j < 4; j++) {
            int idx = tid + (j << 8);
            int gm = m0 + (idx >> 3); if (gm > M - 1) gm = M - 1;
            pf[j] = *(const float4*)(A + (size_t)gm * 128 + ((idx & 7) << 2));
        }
    }
    int buf = 0;

    for (; t < tiles; t += gridDim.x) {
        const int m0 = t << 7;
        float acc[4][4][4] = {};
        for (int kc = 0; kc < 4; kc++) {
            const int kb = kc << 5;
            {
                char* ah_base = smem + buf * A_BUF_B;
                #pragma unroll
                for (int j = 0; j < 4; j++) {
                    int idx = tid + (j << 8);
                    int row = idx >> 3;
                    int c4  = (idx & 7) << 2;
                    float4 v = pf[j];
                    uint32_t h01, l01, h23, l23;
                    split_pair(v.x, v.y, h01, l01);
                    split_pair(v.z, v.w, h23, l23);
                    uint32_t off = ((uint32_t)row * 40 + c4) * 2u;
                    *(uint2*)(ah_base + off)          = make_uint2(h01, h23);
                    *(uint2*)(ah_base + A_CH_B + off) = make_uint2(l01, l23);
                }
            }
            __syncthreads();
            {
                int kc2 = kc + 1, tn = t;
                if (kc2 == 4) { kc2 = 0; tn = t + gridDim.x; }
                if (tn < tiles) {
                    int m2 = tn << 7, kb2 = kc2 << 5;
                    #pragma unroll
                    for (int j = 0; j < 4; j++) {
                        int idx = tid + (j << 8);
                        int gm = m2 + (idx >> 3); if (gm > M - 1) gm = M - 1;
                        pf[j] = *(const float4*)(A + (size_t)gm * 128 + kb2 + ((idx & 7) << 2));
                    }
                }
            }
            const uint32_t abase = sbase + buf * A_BUF_B;
            #pragma unroll
            for (int ks = 0; ks < 2; ks++) {
                const int ka = ks << 4;
                uint32_t bh[4][2], bl[4][2];
                #pragma unroll
                for (int np = 0; np < 2; np++) {
                    uint32_t roff = ((uint32_t)(wn * 32 + np * 16 + b_row) * BS
                                     + kb + ka + b_k) * 2u;
                    uint32_t rh[4], rl[4];
                    ldsm_x4(sbase + B_BASE + roff, rh);
                    ldsm_x4(sbase + B_BASE + BBs + roff, rl);
                    bh[np*2][0] = rh[0]; bh[np*2][1] = rh[1];
                    bh[np*2+1][0] = rh[2]; bh[np*2+1][1] = rh[3];
                    bl[np*2][0] = rl[0]; bl[np*2][1] = rl[1];
                    bl[np*2+1][0] = rl[2]; bl[np*2+1][1] = rl[3];
                }
                uint32_t ah[4][4], al[4][4];
                #pragma unroll
                for (int mt = 0; mt < 4; mt++) {
                    uint32_t roff = ((uint32_t)(wm * 64 + mt * 16 + a_row) * 40
                                     + ka + a_k) * 2u;
                    ldsm_x4(abase + roff, ah[mt]);
                    ldsm_x4(abase + A_CH_B + roff, al[mt]);
                }
                #pragma unroll
                for (int mt = 0; mt < 4; mt++)
                    #pragma unroll
                    for (int nt = 0; nt < 4; nt++) {
                        mma_bf16(acc[mt][nt], ah[mt], bh[nt]);
                        mma_bf16(acc[mt][nt], ah[mt], bl[nt]);
                        mma_bf16(acc[mt][nt], al[mt], bh[nt]);
                    }
            }
            buf ^= 1;
        }

        // ---- fused edge epilogue
        const int g  = lane >> 2;
        const int t2 = (lane & 3) << 1;
        #pragma unroll
        for (int mt = 0; mt < 4; mt++) {
            #pragma unroll
            for (int half = 0; half < 2; half++) {
                int r = m0 + wm * 64 + mt * 16 + g + half * 8;
                bool valid = (r < M);
                int rr = valid ? r : (M - 1);
                int sidx = src[rr];
                int didx = dst[rr];
                float sc[4][2];
                float p0 = 0.f, p1 = 0.f;
                #pragma unroll
                for (int nt = 0; nt < 4; nt++) {
                    int c = wn * 32 + nt * 8 + t2;
                    float2 bv = *(const float2*)(bias + c);
                    float2 kv = *(const float2*)(g_K + (size_t)sidx * 128 + c);
                    float2 qv = *(const float2*)(g_Q + (size_t)didx * 128 + c);
                    float s0 = (acc[mt][nt][half*2]   + bv.x) * kv.x * qv.x * 0.25f;
                    float s1 = (acc[mt][nt][half*2+1] + bv.y) * kv.y * qv.y * 0.25f;
                    sc[nt][0] = s0; sc[nt][1] = s1;
                    if (nt < 2) p0 += s0 + s1; else p1 += s0 + s1;
                }
                p0 += __shfl_xor_sync(0xffffffffu, p0, 1);
                p0 += __shfl_xor_sync(0xffffffffu, p0, 2);
                p1 += __shfl_xor_sync(0xffffffffu, p1, 1);
                p1 += __shfl_xor_sync(0xffffffffu, p1, 2);
                float ss0 = __expf(fminf(fmaxf(p0, -5.f), 5.f));
                float ss1 = __expf(fminf(fmaxf(p1, -5.f), 5.f));
                if (valid) {
                    #pragma unroll
                    for (int nt = 0; nt < 4; nt++) {
                        int c = wn * 32 + nt * 8 + t2;
                        *(float2*)(g_EA + (size_t)r * 128 + c) =
                            make_float2(sc[nt][0], sc[nt][1]);
                        float ss = (nt < 2) ? ss0 : ss1;
                        float2 vv = *(const float2*)(g_V + (size_t)sidx * 128 + c);
                        atomicAdd(&g_wV[(size_t)didx * 128 + c],     vv.x * ss);
                        atomicAdd(&g_wV[(size_t)didx * 128 + c + 1], vv.y * ss);
                    }
                    if ((lane & 3) == 0) {
                        atomicAdd(&g_z[(size_t)didx * 8 + wn * 2],     ss0);
                        atomicAdd(&g_z[(size_t)didx * 8 + wn * 2 + 1], ss1);
                    }
                }
            }
        }
    }
}

// ============================================================================
// FFN1: C[M,256] = relu( (A(*AscAsh)) @ W[128,256] + bias ), single launch.
// ============================================================================
#define F1_A_LO 34816
#define F1_B    69632
#define F1_BBs  69632u

__global__ __launch_bounds__(256, 1)
void k_ffn1(const float* __restrict__ A,
            const __nv_bfloat16* __restrict__ Whi,
            const __nv_bfloat16* __restrict__ Wlo,
            const float* __restrict__ bias, float* __restrict__ C, int M,
            const float* __restrict__ Asc, const float* __restrict__ Ash)
{
    extern __shared__ char smem[];
    const uint32_t sbase = smem_u32(smem);
    const int tid  = threadIdx.x;
    const int lane = tid & 31;
    const int wid  = tid >> 5;
    const int wm   = wid >> 2;
    const int wn   = wid & 3;

    for (int i = tid; i < 256 * 16; i += 256) {
        int k8 = i & 15;
        int n  = i >> 4;
        uint4 vh = *(const uint4*)(Whi + (size_t)n * 128 + (k8 << 3));
        uint4 vl = *(const uint4*)(Wlo + (size_t)n * 128 + (k8 << 3));
        uint32_t off = ((uint32_t)n * 136 + (k8 << 3)) * 2u;
        *(uint4*)(smem + F1_B + off)          = vh;
        *(uint4*)(smem + F1_B + F1_BBs + off) = vl;
    }

    const int tiles = (M + 127) >> 7;
    const int a_row = (lane & 15);
    const int a_k   = (lane >> 4) << 3;
    const int b_row = (lane & 7) + ((lane >> 4) << 3);
    const int b_k   = ((lane >> 3) & 1) << 3;
    const int g  = lane >> 2;
    const int t2 = (lane & 3) << 1;

    for (int t = blockIdx.x; t < tiles; t += gridDim.x) {
        const int m0 = t << 7;
        __syncthreads();
        for (int j = 0; j < 16; j++) {
            int idx = tid + (j << 8);
            int row = idx >> 5;
            int c4  = (idx & 31) << 2;
            int gm = m0 + row; if (gm > M - 1) gm = M - 1;
            float4 v = *(const float4*)(A + (size_t)gm * 128 + c4);
            float4 sc = *(const float4*)(Asc + c4);
            float4 sh = *(const float4*)(Ash + c4);
            v.x = v.x * sc.x + sh.x;
            v.y = v.y * sc.y + sh.y;
            v.z = v.z * sc.z + sh.z;
            v.w = v.w * sc.w + sh.w;
            uint32_t h01, l01, h23, l23;
            split_pair(v.x, v.y, h01, l01);
            split_pair(v.z, v.w, h23, l23);
            uint32_t off = ((uint32_t)row * 136 + c4) * 2u;
            *(uint2*)(smem + off)           = make_uint2(h01, h23);
            *(uint2*)(smem + F1_A_LO + off) = make_uint2(l01, l23);
        }
        __syncthreads();

        for (int nh = 0; nh < 2; nh++) {
            float acc[4][4][4] = {};
            #pragma unroll
            for (int ks = 0; ks < 8; ks++) {
                const int ka = ks << 4;
                uint32_t bh[4][2], bl[4][2];
                #pragma unroll
                for (int np = 0; np < 2; np++) {
                    uint32_t roff = ((uint32_t)(nh * 128 + wn * 32 + np * 16 + b_row) * 136
                                     + ka + b_k) * 2u;
                    uint32_t rh[4], rl[4];
                    ldsm_x4(sbase + F1_B + roff, rh);
                    ldsm_x4(sbase + F1_B + F1_BBs + roff, rl);
                    bh[np*2][0] = rh[0]; bh[np*2][1] = rh[1];
                    bh[np*2+1][0] = rh[2]; bh[np*2+1][1] = rh[3];
                    bl[np*2][0] = rl[0]; bl[np*2][1] = rl[1];
                    bl[np*2+1][0] = rl[2]; bl[np*2+1][1] = rl[3];
                }
                uint32_t ah[4][4], al[4][4];
                #pragma unroll
                for (int mt = 0; mt < 4; mt++) {
                    uint32_t roff = ((uint32_t)(wm * 64 + mt * 16 + a_row) * 136
                                     + ka + a_k) * 2u;
                    ldsm_x4(sbase + roff, ah[mt]);
                    ldsm_x4(sbase + F1_A_LO + roff, al[mt]);
                }
                #pragma unroll
                for (int mt = 0; mt < 4; mt++)
                    #pragma unroll
                    for (int nt = 0; nt < 4; nt++) {
                        mma_bf16(acc[mt][nt], ah[mt], bh[nt]);
                        mma_bf16(acc[mt][nt], ah[mt], bl[nt]);
                        mma_bf16(acc[mt][nt], al[mt], bh[nt]);
                    }
            }
            #pragma unroll
            for (int mt = 0; mt < 4; mt++) {
                int r0 = m0 + wm * 64 + mt * 16 + g;
                #pragma unroll
                for (int nt = 0; nt < 4; nt++) {
                    int c0 = nh * 128 + wn * 32 + nt * 8 + t2;
                    float2 bv = *(const float2*)(bias + c0);
                    #pragma unroll
                    for (int half = 0; half < 2; half++) {
                        int r = r0 + half * 8;
                        if (r >= M) continue;
                        float2 v = make_float2(
                            fmaxf(acc[mt][nt][half*2]   + bv.x, 0.f),
                            fmaxf(acc[mt][nt][half*2+1] + bv.y, 0.f));
                        *(float2*)(C + (size_t)r * 256 + c0) = v;
                    }
                }
            }
        }
    }
}

// ---------------- batch-norm finalize / apply --------------------------------
__global__ void k_bn_finalize(int slot, float Mf,
                              const float* __restrict__ g, const float* __restrict__ b)
{
    int c = threadIdx.x;
    double mu  = g_sum[slot * 128 + c] / (double)Mf;
    double var = g_sq [slot * 128 + c] / (double)Mf - mu * mu;
    float sc = g[c] * rsqrtf((float)var + 1e-5f);
    g_bnsc[slot * 128 + c] = sc;
    g_bnsh[slot * 128 + c] = b[c] - (float)mu * sc;
}

__global__ __launch_bounds__(256)
void k_bn_apply(float* __restrict__ X, size_t M, int slot)
{
    size_t total4 = M * 32;
    size_t i = (size_t)blockIdx.x * blockDim.x + threadIdx.x;
    size_t stride = (size_t)gridDim.x * blockDim.x;
    for (size_t j = i; j < total4; j += stride) {
        int c = (int)(j & 31) * 4;
        const float* sc = g_bnsc + slot * 128 + c;
        const float* sh = g_bnsh + slot * 128 + c;
        float4 v = ((float4*)X)[j];
        v.x = v.x * sc[0] + sh[0];
        v.y = v.y * sc[1] + sh[1];
        v.z = v.z * sc[2] + sh[2];
        v.w = v.w * sc[3] + sh[3];
        ((float4*)X)[j] = v;
    }
}

// ---------------- host orchestration ---------------------------------------
static __nv_bfloat16* wb_base = nullptr;

static void mm4(const float* A, int Ald, int woff,
                const float* bias, const float* res, float* C, int Cld,
                int M, int relu,
                const float* Asc = nullptr, const float* Ash = nullptr,
                const float* Zrow = nullptr,
                const float* Rsc = nullptr, const float* Rsh = nullptr,
                double* sumP = nullptr, double* sqP = nullptr)
{
    int tiles = (M + 127) / 128;
    int grid = tiles < 296 ? tiles : 296;
    k_mmgemm<4><<<grid, 256, 110592>>>(A, Ald, wb_base + woff, wb_base + woff + TOTW,
                                       bias, res, C, Cld, M, relu,
                                       Asc, Ash, Zrow, Rsc, Rsh, sumP, sqP);
}

static void mm8(const float* A, int Ald, int woff,
                const float* bias, const float* res, float* C, int Cld,
                int M,
                const float* Rsc, const float* Rsh,
                double* sumP, double* sqP)
{
    int tiles = (M + 127) / 128;
    int grid = tiles < 148 ? tiles : 148;
    k_mmgemm<8><<<grid, 256, 176128>>>(A, Ald, wb_base + woff, wb_base + woff + TOTW,
                                       bias, res, C, Cld, M, 0,
                                       nullptr, nullptr, nullptr, Rsc, Rsh, sumP, sqP);
}

extern "C" void kernel_launch(void* const* d_in, const int* in_sizes, int n_in,
                              void* d_out, int out_size)
{
    const float* h   = (const float*)d_in[0];
    const float* e   = (const float*)d_in[1];
    const int*   src = (const int*)d_in[2];
    const int*   dst = (const int*)d_in[3];
    const float* WQ  = (const float*)d_in[4];   const float* bQ  = (const float*)d_in[5];
    const float* WK  = (const float*)d_in[6];   const float* bK  = (const float*)d_in[7];
    const float* WV  = (const float*)d_in[8];   const float* bV  = (const float*)d_in[9];
    const float* WE  = (const float*)d_in[10];  const float* bE  = (const float*)d_in[11];
    const float* WOh = (const float*)d_in[12];  const float* bOh = (const float*)d_in[13];
    const float* WOe = (const float*)d_in[14];  const float* bOe = (const float*)d_in[15];
    const float* Wh1 = (const float*)d_in[16];  const float* bh1 = (const float*)d_in[17];
    const float* Wh2 = (const float*)d_in[18];  const float* bh2 = (const float*)d_in[19];
    const float* We1 = (const float*)d_in[20];  const float* be1 = (const float*)d_in[21];
    const float* We2 = (const float*)d_in[22];  const float* be2 = (const float*)d_in[23];
    const float* g1h = (const float*)d_in[24];
    const float* g1e = (const float*)d_in[25];
    const float* g2h = (const float*)d_in[26];
    const float* g2e = (const float*)d_in[27];
    const float* b1h = (const float*)d_in[28];
    const float* b1e = (const float*)d_in[29];
    const float* b2h = (const float*)d_in[30];
    const float* b2e = (const float*)d_in[31];

    float *pQ, *pK, *pV, *ph1, *phidh, *pEA, *pe1, *phide, *pbnsc, *pbnsh, *pwV, *pz;
    double *psum, *psq;
    cudaGetSymbolAddress((void**)&pQ,    g_Q);
    cudaGetSymbolAddress((void**)&pK,    g_K);
    cudaGetSymbolAddress((void**)&pV,    g_V);
    cudaGetSymbolAddress((void**)&ph1,   g_h1);
    cudaGetSymbolAddress((void**)&phidh, g_hidh);
    cudaGetSymbolAddress((void**)&pEA,   g_EA);
    cudaGetSymbolAddress((void**)&pe1,   g_e1);
    cudaGetSymbolAddress((void**)&phide, g_hide);
    cudaGetSymbolAddress((void**)&pbnsc, g_bnsc);
    cudaGetSymbolAddress((void**)&pbnsh, g_bnsh);
    cudaGetSymbolAddress((void**)&pwV,   g_wV);
    cudaGetSymbolAddress((void**)&pz,    g_z);
    cudaGetSymbolAddress((void**)&psum,  g_sum);
    cudaGetSymbolAddress((void**)&psq,   g_sq);
    cudaGetSymbolAddress((void**)&wb_base, g_Wb);

    cudaFuncSetAttribute(k_mmgemm<4>, cudaFuncAttributeMaxDynamicSharedMemorySize, 110592);
    cudaFuncSetAttribute(k_mmgemm<8>, cudaFuncAttributeMaxDynamicSharedMemorySize, 176128);
    cudaFuncSetAttribute(k_eproj,     cudaFuncAttributeMaxDynamicSharedMemorySize, 110592);
    cudaFuncSetAttribute(k_ffn1,      cudaFuncAttributeMaxDynamicSharedMemorySize, 208896);

    float* out_h = (float*)d_out;
    float* out_e = (float*)d_out + (size_t)NN * 128;

    // 0) zero accumulators + BN stats; pre-split weights
    k_zero<<<4096, 256>>>();
    k_wsplit<<<448, 256>>>(WQ, WK, WV, WE, WOh, WOe, Wh1, We1, Wh2, We2);

    // 1) h projections (needed by fused e-projection/edge kernel)
    mm4(h, 128, OFF_WQ, bQ, nullptr, pQ,  128, NN, 0);
    mm4(h, 128, OFF_WK, bK, nullptr, pK,  128, NN, 0);
    mm4(h, 128, OFF_WV, bV, nullptr, pV,  128, NN, 0);

    // 2) fused E-projection + edge attention (writes e_attn, wV, z)
    {
        int ge = (EG + 127) / 128; if (ge > 296) ge = 296;
        k_eproj<<<ge, 256, 110592>>>(e, wb_base + OFF_WE, wb_base + OFF_WE + TOTW,
                                     bE, src, dst, EG);
    }

    // 3+4) O projections; h_attn fused via Zrow; BN1 stats fused
    mm4(pwV, 128, OFF_WOH, bOh, h, ph1, 128, NN, 0,
        nullptr, nullptr, pz, nullptr, nullptr, psum + 0,   psq + 0);
    mm4(pEA, 128, OFF_WOE, bOe, e, pe1, 128, EG, 0,
        nullptr, nullptr, nullptr, nullptr, nullptr, psum + 128, psq + 128);

    // 5) BN #1 finalize
    k_bn_finalize<<<1, 128>>>(0, (float)NN, g1h, b1h);
    k_bn_finalize<<<1, 128>>>(1, (float)EG, g1e, b1e);

    // 6) FFNs
    {
        int gh = (NN + 127) / 128; if (gh > 148) gh = 148;
        k_ffn1<<<gh, 256, 208896>>>(ph1, wb_base + OFF_WH1, wb_base + OFF_WH1 + TOTW,
                                    bh1, phidh, NN, pbnsc + 0, pbnsh + 0);
    }
    mm8(phidh, 256, OFF_WH2, bh2, ph1, out_h, 128, NN,
        pbnsc + 0, pbnsh + 0, psum + 256, psq + 256);
    {
        int ge = (EG + 127) / 128; if (ge > 148) ge = 148;
        k_ffn1<<<ge, 256, 208896>>>(pe1, wb_base + OFF_WE1, wb_base + OFF_WE1 + TOTW,
                                    be1, phide, EG, pbnsc + 128, pbnsh + 128);
    }
    mm8(phide, 256, OFF_WE2, be2, pe1, out_e, 128, EG,
        pbnsc + 128, pbnsh + 128, psum + 384, psq + 384);

    // 7) BN #2 finalize + apply
    k_bn_finalize<<<1, 128>>>(2, (float)NN, g2h, b2h);
    k_bn_apply<<<12800, 256>>>(out_h, (size_t)NN, 2);
    k_bn_finalize<<<1, 128>>>(3, (float)EG, g2e, b2e);
    k_bn_apply<<<100000, 256>>>(out_e, (size_t)EG, 3);
}

// round 10
// speedup vs baseline: 1.2336x; 1.2336x over previous
#include <cuda_runtime.h>
#include <cuda_bf16.h>
#include <cstdint>
#include <math.h>

// Problem constants
#define NN 50000
#define EG 800000

// ---------------- scratch (device globals; no runtime allocation) ----------
__device__ float  g_Q   [(size_t)NN * 128];
__device__ float  g_K   [(size_t)NN * 128];
__device__ float  g_V   [(size_t)NN * 128];
__device__ float  g_h1  [(size_t)NN * 128];
__device__ float  g_wV  [(size_t)NN * 128];
__device__ float  g_z   [(size_t)NN * 8];
__device__ float  g_EA  [(size_t)EG * 128];
__device__ float  g_e1  [(size_t)EG * 128];
__device__ double g_sum [4 * 128];
__device__ double g_sq  [4 * 128];
__device__ float  g_bnsc[4 * 128];
__device__ float  g_bnsh[4 * 128];

// pre-split weights: hi plane [0, TOTW), lo plane [TOTW, 2*TOTW), bf16
#define OFF_WQ   0
#define OFF_WK   16384
#define OFF_WV   32768
#define OFF_WE   49152
#define OFF_WOH  65536
#define OFF_WOE  81920
#define OFF_WH1  98304
#define OFF_WE1  131072
#define OFF_WH2  163840
#define OFF_WE2  196608
#define TOTW     229376
__device__ __nv_bfloat16 g_Wb[2 * TOTW];

// ---------------- zero accumulators ----------------------------------------
__global__ void k_zero() {
    size_t i = (size_t)blockIdx.x * blockDim.x + threadIdx.x;
    size_t stride = (size_t)gridDim.x * blockDim.x;
    for (size_t j = i; j < (size_t)NN * 128; j += stride) g_wV[j] = 0.f;
    for (size_t j = i; j < (size_t)NN * 8;   j += stride) g_z[j]  = 0.f;
    if (i < 512) { g_sum[i] = 0.0; g_sq[i] = 0.0; }
}

// ============================================================================
// helpers
// ============================================================================
__device__ __forceinline__ uint32_t smem_u32(const void* p) {
    uint32_t a;
    asm("{ .reg .u64 t; cvta.to.shared.u64 t, %1; cvt.u32.u64 %0, t; }"
        : "=r"(a) : "l"(p));
    return a;
}

__device__ __forceinline__ void ldsm_x4(uint32_t addr, uint32_t* r) {
    asm volatile("ldmatrix.sync.aligned.m8n8.x4.shared.b16 {%0,%1,%2,%3}, [%4];"
        : "=r"(r[0]), "=r"(r[1]), "=r"(r[2]), "=r"(r[3]) : "r"(addr));
}

__device__ __forceinline__ void mma_bf16(float* acc, const uint32_t* a, const uint32_t* b) {
    asm volatile(
        "mma.sync.aligned.m16n8k16.row.col.f32.bf16.bf16.f32 "
        "{%0,%1,%2,%3},{%4,%5,%6,%7},{%8,%9},{%0,%1,%2,%3};"
        : "+f"(acc[0]), "+f"(acc[1]), "+f"(acc[2]), "+f"(acc[3])
        : "r"(a[0]), "r"(a[1]), "r"(a[2]), "r"(a[3]), "r"(b[0]), "r"(b[1]));
}

__device__ __forceinline__ void split_pair(float x0, float x1, uint32_t& hi, uint32_t& lo)
{
    __nv_bfloat162 h = __floats2bfloat162_rn(x0, x1);
    float r0 = x0 - __bfloat162float(__low2bfloat16(h));
    float r1 = x1 - __bfloat162float(__high2bfloat16(h));
    __nv_bfloat162 l = __floats2bfloat162_rn(r0, r1);
    hi = *reinterpret_cast<uint32_t*>(&h);
    lo = *reinterpret_cast<uint32_t*>(&l);
}

// ============================================================================
// Weight pre-split
// ============================================================================
__global__ __launch_bounds__(256)
void k_wsplit(const float* __restrict__ WQ,  const float* __restrict__ WK,
              const float* __restrict__ WV,  const float* __restrict__ WE,
              const float* __restrict__ WOh, const float* __restrict__ WOe,
              const float* __restrict__ Wh1, const float* __restrict__ We1,
              const float* __restrict__ Wh2, const float* __restrict__ We2)
{
    int p = blockIdx.x * 256 + threadIdx.x;
    if (p >= TOTW / 2) return;
    const float* W;
    int Kd, Nd, local, base;
    if (p < 49152) {
        int m = p >> 13;
        local = p & 8191;
        Kd = 128; Nd = 128; base = m << 14;
        W = (m == 0) ? WQ : (m == 1) ? WK : (m == 2) ? WV :
            (m == 3) ? WE : (m == 4) ? WOh : WOe;
    } else if (p < 65536)  { local = p - 49152; Kd = 128; Nd = 256; base = OFF_WH1; W = Wh1; }
    else if (p < 81920)    { local = p - 65536; Kd = 128; Nd = 256; base = OFF_WE1; W = We1; }
    else if (p < 98304)    { local = p - 81920; Kd = 256; Nd = 128; base = OFF_WH2; W = Wh2; }
    else                   { local = p - 98304; Kd = 256; Nd = 128; base = OFF_WE2; W = We2; }
    int n  = local % Nd;
    int k  = (local / Nd) * 2;
    float x0 = W[(size_t)k * Nd + n];
    float x1 = W[(size_t)(k + 1) * Nd + n];
    uint32_t hi, lo;
    split_pair(x0, x1, hi, lo);
    size_t o = (size_t)base + (size_t)n * Kd + k;
    *(uint32_t*)((char*)g_Wb + o * 2)          = hi;
    *(uint32_t*)((char*)g_Wb + (o + TOTW) * 2) = lo;
}

// ============================================================================
// Pipelined HMMA bf16 3-split GEMM. K = 128, N = 128.
// C = [res +] (A(/Zrow)) @ W + bias; optional fused BN column stats.
// ============================================================================
#define A_CH_B 10240
#define A_BUF_B 20480
#define B_BASE 40960

__global__ __launch_bounds__(256, 2)
void k_mmgemm(const float* __restrict__ A, int Ald,
              const __nv_bfloat16* __restrict__ Whi,
              const __nv_bfloat16* __restrict__ Wlo,
              const float* __restrict__ bias, const float* __restrict__ res,
              float* __restrict__ C, int Cld, int M,
              const float* __restrict__ Zrow,
              double* sumP, double* sqP)
{
    extern __shared__ char smem[];
    constexpr int BS = 136;
    constexpr uint32_t BBs = 128u * BS * 2u;
    const uint32_t sbase = smem_u32(smem);

    const int tid  = threadIdx.x;
    const int lane = tid & 31;
    const int wid  = tid >> 5;
    const int wm   = wid >> 2;
    const int wn   = wid & 3;

    for (int i = tid; i < 128 * 16; i += 256) {
        int k8 = i & 15;
        int n  = i >> 4;
        uint4 vh = *(const uint4*)(Whi + (size_t)n * 128 + (k8 << 3));
        uint4 vl = *(const uint4*)(Wlo + (size_t)n * 128 + (k8 << 3));
        uint32_t off = ((uint32_t)n * BS + (k8 << 3)) * 2u;
        *(uint4*)(smem + B_BASE + off)       = vh;
        *(uint4*)(smem + B_BASE + BBs + off) = vl;
    }

    const int tiles = (M + 127) >> 7;
    const int a_row = (lane & 15);
    const int a_k   = (lane >> 4) << 3;
    const int b_row = (lane & 7) + ((lane >> 4) << 3);
    const int b_k   = ((lane >> 3) & 1) << 3;

    float4 pf[4];
    int t = blockIdx.x;
    if (t < tiles) {
        int m0 = t << 7;
        #pragma unroll
        for (int j = 0; j < 4; j++) {
            int idx = tid + (j << 8);
            int gm = m0 + (idx >> 3); if (gm > M - 1) gm = M - 1;
            pf[j] = *(const float4*)(A + (size_t)gm * Ald + ((idx & 7) << 2));
        }
    }
    int buf = 0;

    for (; t < tiles; t += gridDim.x) {
        const int m0 = t << 7;
        float acc[4][4][4] = {};
        for (int kc = 0; kc < 4; kc++) {
            const int kb = kc << 5;
            {
                char* ah_base = smem + buf * A_BUF_B;
                #pragma unroll
                for (int j = 0; j < 4; j++) {
                    int idx = tid + (j << 8);
                    int row = idx >> 3;
                    int c4  = (idx & 7) << 2;
                    float4 v = pf[j];
                    if (Zrow) {
                        int gm = m0 + row; if (gm > M - 1) gm = M - 1;
                        float zz = 1.0f / (Zrow[(size_t)gm * 8 + ((kb + c4) >> 4)] + 1e-6f);
                        v.x *= zz; v.y *= zz; v.z *= zz; v.w *= zz;
                    }
                    uint32_t h01, l01, h23, l23;
                    split_pair(v.x, v.y, h01, l01);
                    split_pair(v.z, v.w, h23, l23);
                    uint32_t off = ((uint32_t)row * 40 + c4) * 2u;
                    *(uint2*)(ah_base + off)          = make_uint2(h01, h23);
                    *(uint2*)(ah_base + A_CH_B + off) = make_uint2(l01, l23);
                }
            }
            __syncthreads();
            {
                int kc2 = kc + 1, tn = t;
                if (kc2 == 4) { kc2 = 0; tn = t + gridDim.x; }
                if (tn < tiles) {
                    int m2 = tn << 7, kb2 = kc2 << 5;
                    #pragma unroll
                    for (int j = 0; j < 4; j++) {
                        int idx = tid + (j << 8);
                        int gm = m2 + (idx >> 3); if (gm > M - 1) gm = M - 1;
                        pf[j] = *(const float4*)(A + (size_t)gm * Ald + kb2 + ((idx & 7) << 2));
                    }
                }
            }
            const uint32_t abase = sbase + buf * A_BUF_B;
            #pragma unroll
            for (int ks = 0; ks < 2; ks++) {
                const int ka = ks << 4;
                uint32_t bh[4][2], bl[4][2];
                #pragma unroll
                for (int np = 0; np < 2; np++) {
                    uint32_t roff = ((uint32_t)(wn * 32 + np * 16 + b_row) * BS
                                     + kb + ka + b_k) * 2u;
                    uint32_t rh[4], rl[4];
                    ldsm_x4(sbase + B_BASE + roff, rh);
                    ldsm_x4(sbase + B_BASE + BBs + roff, rl);
                    bh[np*2][0] = rh[0]; bh[np*2][1] = rh[1];
                    bh[np*2+1][0] = rh[2]; bh[np*2+1][1] = rh[3];
                    bl[np*2][0] = rl[0]; bl[np*2][1] = rl[1];
                    bl[np*2+1][0] = rl[2]; bl[np*2+1][1] = rl[3];
                }
                uint32_t ah[4][4], al[4][4];
                #pragma unroll
                for (int mt = 0; mt < 4; mt++) {
                    uint32_t roff = ((uint32_t)(wm * 64 + mt * 16 + a_row) * 40
                                     + ka + a_k) * 2u;
                    ldsm_x4(abase + roff, ah[mt]);
                    ldsm_x4(abase + A_CH_B + roff, al[mt]);
                }
                #pragma unroll
                for (int mt = 0; mt < 4; mt++)
                    #pragma unroll
                    for (int nt = 0; nt < 4; nt++) {
                        mma_bf16(acc[mt][nt], ah[mt], bh[nt]);
                        mma_bf16(acc[mt][nt], ah[mt], bl[nt]);
                        mma_bf16(acc[mt][nt], al[mt], bh[nt]);
                    }
            }
            buf ^= 1;
        }

        const int g  = lane >> 2;
        const int t2 = (lane & 3) << 1;
        #pragma unroll
        for (int nt = 0; nt < 4; nt++) {
            int c0 = wn * 32 + nt * 8 + t2;
            float2 bv = *(const float2*)(bias + c0);
            float ps0 = 0.f, ps1 = 0.f, q0 = 0.f, q1 = 0.f;
            #pragma unroll
            for (int mt = 0; mt < 4; mt++) {
                #pragma unroll
                for (int half = 0; half < 2; half++) {
                    int r = m0 + wm * 64 + mt * 16 + g + half * 8;
                    float2 v = make_float2(acc[mt][nt][half*2]   + bv.x,
                                           acc[mt][nt][half*2+1] + bv.y);
                    if (r < M) {
                        size_t o = (size_t)r * Cld + c0;
                        if (res) {
                            float2 rv = *(const float2*)(res + o);
                            v.x += rv.x; v.y += rv.y;
                        }
                        *(float2*)(C + o) = v;
                    } else { v.x = 0.f; v.y = 0.f; }
                    ps0 += v.x; q0 += v.x * v.x;
                    ps1 += v.y; q1 += v.y * v.y;
                }
            }
            if (sumP) {
                #pragma unroll
                for (int off = 16; off >= 4; off >>= 1) {
                    ps0 += __shfl_down_sync(0xffffffffu, ps0, off);
                    ps1 += __shfl_down_sync(0xffffffffu, ps1, off);
                    q0  += __shfl_down_sync(0xffffffffu, q0,  off);
                    q1  += __shfl_down_sync(0xffffffffu, q1,  off);
                }
                if (lane < 4) {
                    int cc = wn * 32 + nt * 8 + lane * 2;
                    atomicAdd(&sumP[cc],     (double)ps0);
                    atomicAdd(&sumP[cc + 1], (double)ps1);
                    atomicAdd(&sqP[cc],      (double)q0);
                    atomicAdd(&sqP[cc + 1],  (double)q1);
                }
            }
        }
    }
}

// ============================================================================
// Fused FFN: out = bn1(x) + relu(bn1(x)@W1 + b1)@W2 + b2, BN2 stats fused.
// Per 128-row tile: hidden [128x256] lives ONLY in smem (hi/lo bf16, two
// 128-col halves sequentially). W1/W2 streamed through one smem slot in 4
// stages per tile (weights stay L2-hot). Residual = hi+lo reconstruction of
// the staged bn1(x) tile (no gmem re-read).
// smem: A 0/34816, H 69632/104448, W 139264/174080, total 208896.
// ============================================================================
#define FF_A_HI 0
#define FF_A_LO 34816
#define FF_H_HI 69632
#define FF_H_LO 104448
#define FF_W_HI 139264
#define FF_W_LO 174080

__device__ __forceinline__ void ff_gemm(uint32_t sbase, uint32_t aHi, uint32_t aLo,
                                        int lane, int wm, int wn, float acc[4][4][4])
{
    const int a_row = (lane & 15);
    const int a_k   = (lane >> 4) << 3;
    const int b_row = (lane & 7) + ((lane >> 4) << 3);
    const int b_k   = ((lane >> 3) & 1) << 3;
    #pragma unroll
    for (int ks = 0; ks < 8; ks++) {
        const int ka = ks << 4;
        uint32_t bh[4][2], bl[4][2];
        #pragma unroll
        for (int np = 0; np < 2; np++) {
            uint32_t roff = ((uint32_t)(wn * 32 + np * 16 + b_row) * 136 + ka + b_k) * 2u;
            uint32_t rh[4], rl[4];
            ldsm_x4(sbase + FF_W_HI + roff, rh);
            ldsm_x4(sbase + FF_W_LO + roff, rl);
            bh[np*2][0] = rh[0]; bh[np*2][1] = rh[1];
            bh[np*2+1][0] = rh[2]; bh[np*2+1][1] = rh[3];
            bl[np*2][0] = rl[0]; bl[np*2][1] = rl[1];
            bl[np*2+1][0] = rl[2]; bl[np*2+1][1] = rl[3];
        }
        uint32_t ah[4][4], al[4][4];
        #pragma unroll
        for (int mt = 0; mt < 4; mt++) {
            uint32_t roff = ((uint32_t)(wm * 64 + mt * 16 + a_row) * 136 + ka + a_k) * 2u;
            ldsm_x4(sbase + aHi + roff, ah[mt]);
            ldsm_x4(sbase + aLo + roff, al[mt]);
        }
        #pragma unroll
        for (int mt = 0; mt < 4; mt++)
            #pragma unroll
            for (int nt = 0; nt < 4; nt++) {
                mma_bf16(acc[mt][nt], ah[mt], bh[nt]);
                mma_bf16(acc[mt][nt], ah[mt], bl[nt]);
                mma_bf16(acc[mt][nt], al[mt], bh[nt]);
            }
    }
}

__global__ __launch_bounds__(256, 1)
void k_ffnfused(const float* __restrict__ A, int M,
                const __nv_bfloat16* __restrict__ W1hi,
                const __nv_bfloat16* __restrict__ W1lo,
                const float* __restrict__ b1,
                const __nv_bfloat16* __restrict__ W2hi,
                const __nv_bfloat16* __restrict__ W2lo,
                const float* __restrict__ b2,
                float* __restrict__ C,
                const float* __restrict__ Asc, const float* __restrict__ Ash,
                double* sumP, double* sqP)
{
    extern __shared__ char smem[];
    const uint32_t sbase = smem_u32(smem);
    const int tid  = threadIdx.x;
    const int lane = tid & 31;
    const int wid  = tid >> 5;
    const int wm   = wid >> 2;
    const int wn   = wid & 3;
    const int g    = lane >> 2;
    const int t2   = (lane & 3) << 1;
    const int tiles = (M + 127) >> 7;

    for (int t = blockIdx.x; t < tiles; t += gridDim.x) {
        const int m0 = t << 7;
        __syncthreads();  // prev tile fully done (A/H/W free)

        // ---- stage A = bn1(x) tile [128][136] hi/lo; W slot <- W1 half 0
        for (int j = 0; j < 16; j++) {
            int idx = tid + (j << 8);
            int row = idx >> 5;
            int c4  = (idx & 31) << 2;
            int gm = m0 + row; if (gm > M - 1) gm = M - 1;
            float4 v = *(const float4*)(A + (size_t)gm * 128 + c4);
            float4 sc = *(const float4*)(Asc + c4);
            float4 sh = *(const float4*)(Ash + c4);
            v.x = v.x * sc.x + sh.x;
            v.y = v.y * sc.y + sh.y;
            v.z = v.z * sc.z + sh.z;
            v.w = v.w * sc.w + sh.w;
            uint32_t h01, l01, h23, l23;
            split_pair(v.x, v.y, h01, l01);
            split_pair(v.z, v.w, h23, l23);
            uint32_t off = ((uint32_t)row * 136 + c4) * 2u;
            *(uint2*)(smem + FF_A_HI + off) = make_uint2(h01, h23);
            *(uint2*)(smem + FF_A_LO + off) = make_uint2(l01, l23);
        }
        for (int i = tid; i < 2048; i += 256) {
            int n = i >> 4, k8 = i & 15;
            uint4 vh = *(const uint4*)(W1hi + (size_t)n * 128 + (k8 << 3));
            uint4 vl = *(const uint4*)(W1lo + (size_t)n * 128 + (k8 << 3));
            uint32_t off = ((uint32_t)n * 136 + (k8 << 3)) * 2u;
            *(uint4*)(smem + FF_W_HI + off) = vh;
            *(uint4*)(smem + FF_W_LO + off) = vl;
        }
        __syncthreads();

        float acc2[4][4][4] = {};
        #pragma unroll
        for (int nh = 0; nh < 2; nh++) {
            // GEMM1: H_half = A @ W1[:, nh*128:...]
            float acc1[4][4][4] = {};
            ff_gemm(sbase, FF_A_HI, FF_A_LO, lane, wm, wn, acc1);
            __syncthreads();   // all warps done reading Wslot (and H free)
            // write H = relu(acc1 + b1half), split hi/lo
            #pragma unroll
            for (int mt = 0; mt < 4; mt++) {
                #pragma unroll
                for (int nt = 0; nt < 4; nt++) {
                    int c = wn * 32 + nt * 8 + t2;
                    float2 bv = *(const float2*)(b1 + nh * 128 + c);
                    #pragma unroll
                    for (int half = 0; half < 2; half++) {
                        int rloc = wm * 64 + mt * 16 + g + half * 8;
                        float v0 = fmaxf(acc1[mt][nt][half*2]   + bv.x, 0.f);
                        float v1 = fmaxf(acc1[mt][nt][half*2+1] + bv.y, 0.f);
                        uint32_t hi, lo;
                        split_pair(v0, v1, hi, lo);
                        uint32_t off = ((uint32_t)rloc * 136 + c) * 2u;
                        *(uint32_t*)(smem + FF_H_HI + off) = hi;
                        *(uint32_t*)(smem + FF_H_LO + off) = lo;
                    }
                }
            }
            // W slot <- W2 rows [nh*128 : nh*128+128) i.e. k-slice of [128][256]
            for (int i = tid; i < 2048; i += 256) {
                int n = i >> 4, k8 = i & 15;
                uint4 vh = *(const uint4*)(W2hi + (size_t)n * 256 + nh * 128 + (k8 << 3));
                uint4 vl = *(const uint4*)(W2lo + (size_t)n * 256 + nh * 128 + (k8 << 3));
                uint32_t off = ((uint32_t)n * 136 + (k8 << 3)) * 2u;
                *(uint4*)(smem + FF_W_HI + off) = vh;
                *(uint4*)(smem + FF_W_LO + off) = vl;
            }
            __syncthreads();
            // GEMM2 partial: acc2 += H @ W2slice
            ff_gemm(sbase, FF_H_HI, FF_H_LO, lane, wm, wn, acc2);
            if (nh == 0) {
                __syncthreads();   // Wslot free before loading W1 half 1
                for (int i = tid; i < 2048; i += 256) {
                    int n = i >> 4, k8 = i & 15;
                    uint4 vh = *(const uint4*)(W1hi + (size_t)(128 + n) * 128 + (k8 << 3));
                    uint4 vl = *(const uint4*)(W1lo + (size_t)(128 + n) * 128 + (k8 << 3));
                    uint32_t off = ((uint32_t)n * 136 + (k8 << 3)) * 2u;
                    *(uint4*)(smem + FF_W_HI + off) = vh;
                    *(uint4*)(smem + FF_W_LO + off) = vl;
                }
                __syncthreads();
            }
        }

        // ---- epilogue: C = acc2 + b2 + residual(A hi+lo), BN2 stats
        #pragma unroll
        for (int nt = 0; nt < 4; nt++) {
            int c0 = wn * 32 + nt * 8 + t2;
            float2 bv = *(const float2*)(b2 + c0);
            float ps0 = 0.f, ps1 = 0.f, q0 = 0.f, q1 = 0.f;
            #pragma unroll
            for (int mt = 0; mt < 4; mt++) {
                #pragma unroll
                for (int half = 0; half < 2; half++) {
                    int rloc = wm * 64 + mt * 16 + g + half * 8;
                    int r = m0 + rloc;
                    uint32_t off = ((uint32_t)rloc * 136 + c0) * 2u;
                    __nv_bfloat162 rh = *(__nv_bfloat162*)(smem + FF_A_HI + off);
                    __nv_bfloat162 rl = *(__nv_bfloat162*)(smem + FF_A_LO + off);
                    float2 v;
                    v.x = acc2[mt][nt][half*2]   + bv.x
                        + __bfloat162float(__low2bfloat16(rh))
                        + __bfloat162float(__low2bfloat16(rl));
                    v.y = acc2[mt][nt][half*2+1] + bv.y
                        + __bfloat162float(__high2bfloat16(rh))
                        + __bfloat162float(__high2bfloat16(rl));
                    if (r < M) {
                        *(float2*)(C + (size_t)r * 128 + c0) = v;
                    } else { v.x = 0.f; v.y = 0.f; }
                    ps0 += v.x; q0 += v.x * v.x;
                    ps1 += v.y; q1 += v.y * v.y;
                }
            }
            #pragma unroll
            for (int off = 16; off >= 4; off >>= 1) {
                ps0 += __shfl_down_sync(0xffffffffu, ps0, off);
                ps1 += __shfl_down_sync(0xffffffffu, ps1, off);
                q0  += __shfl_down_sync(0xffffffffu, q0,  off);
                q1  += __shfl_down_sync(0xffffffffu, q1,  off);
            }
            if (lane < 4) {
                int cc = wn * 32 + nt * 8 + lane * 2;
                atomicAdd(&sumP[cc],     (double)ps0);
                atomicAdd(&sumP[cc + 1], (double)ps1);
                atomicAdd(&sqP[cc],      (double)q0);
                atomicAdd(&sqP[cc + 1],  (double)q1);
            }
        }
    }
}

// ---------------- edge kernel: 4-edge batched, hoisted gathers ---------------
__global__ __launch_bounds__(256)
void k_edge(const int* __restrict__ src, const int* __restrict__ dst)
{
    const int t  = threadIdx.x & 127;
    const int e0 = blockIdx.x * 8 + (threadIdx.x >> 7) * 4;
    int s[4], d[4];
    #pragma unroll
    for (int i = 0; i < 4; i++) { s[i] = src[e0 + i]; d[i] = dst[e0 + i]; }
    float kv[4], qv[4], vv[4], ev[4];
    #pragma unroll
    for (int i = 0; i < 4; i++) {
        kv[i] = g_K[(size_t)s[i] * 128 + t];
        qv[i] = g_Q[(size_t)d[i] * 128 + t];
        vv[i] = g_V[(size_t)s[i] * 128 + t];
        ev[i] = g_EA[(size_t)(e0 + i) * 128 + t];
    }
    #pragma unroll
    for (int i = 0; i < 4; i++) {
        float sc = kv[i] * qv[i] * 0.25f * ev[i];
        g_EA[(size_t)(e0 + i) * 128 + t] = sc;
        float sum = sc;
        #pragma unroll
        for (int off = 8; off; off >>= 1)
            sum += __shfl_xor_sync(0xffffffffu, sum, off, 16);
        sum = fminf(fmaxf(sum, -5.f), 5.f);
        float ss = __expf(sum);
        atomicAdd(&g_wV[(size_t)d[i] * 128 + t], vv[i] * ss);
        if ((t & 15) == 0)
            atomicAdd(&g_z[(size_t)d[i] * 8 + (t >> 4)], ss);
    }
}

// ---------------- batch-norm finalize / apply --------------------------------
__global__ void k_bn_finalize(int slot, float Mf,
                              const float* __restrict__ g, const float* __restrict__ b)
{
    int c = threadIdx.x;
    double mu  = g_sum[slot * 128 + c] / (double)Mf;
    double var = g_sq [slot * 128 + c] / (double)Mf - mu * mu;
    float sc = g[c] * rsqrtf((float)var + 1e-5f);
    g_bnsc[slot * 128 + c] = sc;
    g_bnsh[slot * 128 + c] = b[c] - (float)mu * sc;
}

__global__ __launch_bounds__(256)
void k_bn_apply(float* __restrict__ X, size_t M, int slot)
{
    size_t total4 = M * 32;
    size_t i = (size_t)blockIdx.x * blockDim.x + threadIdx.x;
    size_t stride = (size_t)gridDim.x * blockDim.x;
    for (size_t j = i; j < total4; j += stride) {
        int c = (int)(j & 31) * 4;
        const float* sc = g_bnsc + slot * 128 + c;
        const float* sh = g_bnsh + slot * 128 + c;
        float4 v = ((float4*)X)[j];
        v.x = v.x * sc[0] + sh[0];
        v.y = v.y * sc[1] + sh[1];
        v.z = v.z * sc[2] + sh[2];
        v.w = v.w * sc[3] + sh[3];
        ((float4*)X)[j] = v;
    }
}

// ---------------- host orchestration ---------------------------------------
static __nv_bfloat16* wb_base = nullptr;

static void mm4(const float* A, int woff,
                const float* bias, const float* res, float* C,
                int M,
                const float* Zrow = nullptr,
                double* sumP = nullptr, double* sqP = nullptr)
{
    int tiles = (M + 127) / 128;
    int grid = tiles < 296 ? tiles : 296;
    k_mmgemm<<<grid, 256, 110592>>>(A, 128, wb_base + woff, wb_base + woff + TOTW,
                                    bias, res, C, 128, M, Zrow, sumP, sqP);
}

extern "C" void kernel_launch(void* const* d_in, const int* in_sizes, int n_in,
                              void* d_out, int out_size)
{
    const float* h   = (const float*)d_in[0];
    const float* e   = (const float*)d_in[1];
    const int*   src = (const int*)d_in[2];
    const int*   dst = (const int*)d_in[3];
    const float* WQ  = (const float*)d_in[4];   const float* bQ  = (const float*)d_in[5];
    const float* WK  = (const float*)d_in[6];   const float* bK  = (const float*)d_in[7];
    const float* WV  = (const float*)d_in[8];   const float* bV  = (const float*)d_in[9];
    const float* WE  = (const float*)d_in[10];  const float* bE  = (const float*)d_in[11];
    const float* WOh = (const float*)d_in[12];  const float* bOh = (const float*)d_in[13];
    const float* WOe = (const float*)d_in[14];  const float* bOe = (const float*)d_in[15];
    const float* Wh1 = (const float*)d_in[16];  const float* bh1 = (const float*)d_in[17];
    const float* Wh2 = (const float*)d_in[18];  const float* bh2 = (const float*)d_in[19];
    const float* We1 = (const float*)d_in[20];  const float* be1 = (const float*)d_in[21];
    const float* We2 = (const float*)d_in[22];  const float* be2 = (const float*)d_in[23];
    const float* g1h = (const float*)d_in[24];
    const float* g1e = (const float*)d_in[25];
    const float* g2h = (const float*)d_in[26];
    const float* g2e = (const float*)d_in[27];
    const float* b1h = (const float*)d_in[28];
    const float* b1e = (const float*)d_in[29];
    const float* b2h = (const float*)d_in[30];
    const float* b2e = (const float*)d_in[31];

    float *pQ, *pK, *pV, *ph1, *pEA, *pe1, *pbnsc, *pbnsh, *pwV, *pz;
    double *psum, *psq;
    cudaGetSymbolAddress((void**)&pQ,    g_Q);
    cudaGetSymbolAddress((void**)&pK,    g_K);
    cudaGetSymbolAddress((void**)&pV,    g_V);
    cudaGetSymbolAddress((void**)&ph1,   g_h1);
    cudaGetSymbolAddress((void**)&pEA,   g_EA);
    cudaGetSymbolAddress((void**)&pe1,   g_e1);
    cudaGetSymbolAddress((void**)&pbnsc, g_bnsc);
    cudaGetSymbolAddress((void**)&pbnsh, g_bnsh);
    cudaGetSymbolAddress((void**)&pwV,   g_wV);
    cudaGetSymbolAddress((void**)&pz,    g_z);
    cudaGetSymbolAddress((void**)&psum,  g_sum);
    cudaGetSymbolAddress((void**)&psq,   g_sq);
    cudaGetSymbolAddress((void**)&wb_base, g_Wb);

    cudaFuncSetAttribute(k_mmgemm,   cudaFuncAttributeMaxDynamicSharedMemorySize, 110592);
    cudaFuncSetAttribute(k_ffnfused, cudaFuncAttributeMaxDynamicSharedMemorySize, 208896);

    float* out_h = (float*)d_out;
    float* out_e = (float*)d_out + (size_t)NN * 128;

    // 0) zero accumulators + BN stats; pre-split weights
    k_zero<<<4096, 256>>>();
    k_wsplit<<<448, 256>>>(WQ, WK, WV, WE, WOh, WOe, Wh1, We1, Wh2, We2);

    // 1) projections
    mm4(h, OFF_WQ, bQ, nullptr, pQ,  NN);
    mm4(h, OFF_WK, bK, nullptr, pK,  NN);
    mm4(h, OFF_WV, bV, nullptr, pV,  NN);
    mm4(e, OFF_WE, bE, nullptr, pEA, EG);

    // 2) edge scores + attention weights + segment sums
    k_edge<<<EG / 8, 256>>>(src, dst);

    // 3+4) O projections; h_attn fused via Zrow; BN1 stats fused
    mm4(pwV, OFF_WOH, bOh, h, ph1, NN, pz, psum + 0,   psq + 0);
    mm4(pEA, OFF_WOE, bOe, e, pe1, EG, nullptr, psum + 128, psq + 128);

    // 5) BN #1 finalize
    k_bn_finalize<<<1, 128>>>(0, (float)NN, g1h, b1h);
    k_bn_finalize<<<1, 128>>>(1, (float)EG, g1e, b1e);

    // 6) fused FFNs (BN1 applied on input; hidden smem-only; BN2 stats fused)
    {
        int gh = (NN + 127) / 128; if (gh > 148) gh = 148;
        k_ffnfused<<<gh, 256, 208896>>>(ph1, NN,
            wb_base + OFF_WH1, wb_base + OFF_WH1 + TOTW, bh1,
            wb_base + OFF_WH2, wb_base + OFF_WH2 + TOTW, bh2,
            out_h, pbnsc + 0, pbnsh + 0, psum + 256, psq + 256);
    }
    {
        int ge = (EG + 127) / 128; if (ge > 148) ge = 148;
        k_ffnfused<<<ge, 256, 208896>>>(pe1, EG,
            wb_base + OFF_WE1, wb_base + OFF_WE1 + TOTW, be1,
            wb_base + OFF_WE2, wb_base + OFF_WE2 + TOTW, be2,
            out_e, pbnsc + 128, pbnsh + 128, psum + 384, psq + 384);
    }

    // 7) BN #2 finalize + apply
    k_bn_finalize<<<1, 128>>>(2, (float)NN, g2h, b2h);
    k_bn_apply<<<12800, 256>>>(out_h, (size_t)NN, 2);
    k_bn_finalize<<<1, 128>>>(3, (float)EG, g2e, b2e);
    k_bn_apply<<<100000, 256>>>(out_e, (size_t)EG, 3);
}

// round 11
// speedup vs baseline: 1.2575x; 1.0194x over previous
#include <cuda_runtime.h>
#include <cuda_bf16.h>
#include <cstdint>
#include <math.h>

// Problem constants
#define NN 50000
#define EG 800000

// ---------------- scratch (device globals; no runtime allocation) ----------
__device__ float  g_Q   [(size_t)NN * 128];
__device__ float  g_K   [(size_t)NN * 128];
__device__ float  g_V   [(size_t)NN * 128];
__device__ float  g_h1  [(size_t)NN * 128];
__device__ float  g_wV  [(size_t)NN * 128];
__device__ float  g_z   [(size_t)NN * 8];
__device__ float  g_EA  [(size_t)EG * 128];
__device__ float  g_e1  [(size_t)EG * 128];
__device__ double g_sum [4 * 128];
__device__ double g_sq  [4 * 128];
__device__ float  g_bnsc[4 * 128];
__device__ float  g_bnsh[4 * 128];

// pre-split weights: hi plane [0, TOTW), lo plane [TOTW, 2*TOTW), bf16
#define OFF_WQ   0
#define OFF_WK   16384
#define OFF_WV   32768
#define OFF_WE   49152
#define OFF_WOH  65536
#define OFF_WOE  81920
#define OFF_WH1  98304
#define OFF_WE1  131072
#define OFF_WH2  163840
#define OFF_WE2  196608
#define TOTW     229376
__device__ __nv_bfloat16 g_Wb[2 * TOTW];

// ---------------- zero accumulators ----------------------------------------
__global__ void k_zero() {
    size_t i = (size_t)blockIdx.x * blockDim.x + threadIdx.x;
    size_t stride = (size_t)gridDim.x * blockDim.x;
    for (size_t j = i; j < (size_t)NN * 128; j += stride) g_wV[j] = 0.f;
    for (size_t j = i; j < (size_t)NN * 8;   j += stride) g_z[j]  = 0.f;
    if (i < 512) { g_sum[i] = 0.0; g_sq[i] = 0.0; }
}

// ============================================================================
// helpers
// ============================================================================
__device__ __forceinline__ uint32_t smem_u32(const void* p) {
    uint32_t a;
    asm("{ .reg .u64 t; cvta.to.shared.u64 t, %1; cvt.u32.u64 %0, t; }"
        : "=r"(a) : "l"(p));
    return a;
}

__device__ __forceinline__ void ldsm_x4(uint32_t addr, uint32_t* r) {
    asm volatile("ldmatrix.sync.aligned.m8n8.x4.shared.b16 {%0,%1,%2,%3}, [%4];"
        : "=r"(r[0]), "=r"(r[1]), "=r"(r[2]), "=r"(r[3]) : "r"(addr));
}

__device__ __forceinline__ void mma_bf16(float* acc, const uint32_t* a, const uint32_t* b) {
    asm volatile(
        "mma.sync.aligned.m16n8k16.row.col.f32.bf16.bf16.f32 "
        "{%0,%1,%2,%3},{%4,%5,%6,%7},{%8,%9},{%0,%1,%2,%3};"
        : "+f"(acc[0]), "+f"(acc[1]), "+f"(acc[2]), "+f"(acc[3])
        : "r"(a[0]), "r"(a[1]), "r"(a[2]), "r"(a[3]), "r"(b[0]), "r"(b[1]));
}

__device__ __forceinline__ void split_pair(float x0, float x1, uint32_t& hi, uint32_t& lo)
{
    __nv_bfloat162 h = __floats2bfloat162_rn(x0, x1);
    float r0 = x0 - __bfloat162float(__low2bfloat16(h));
    float r1 = x1 - __bfloat162float(__high2bfloat16(h));
    __nv_bfloat162 l = __floats2bfloat162_rn(r0, r1);
    hi = *reinterpret_cast<uint32_t*>(&h);
    lo = *reinterpret_cast<uint32_t*>(&l);
}

// ============================================================================
// Weight pre-split
// ============================================================================
__global__ __launch_bounds__(256)
void k_wsplit(const float* __restrict__ WQ,  const float* __restrict__ WK,
              const float* __restrict__ WV,  const float* __restrict__ WE,
              const float* __restrict__ WOh, const float* __restrict__ WOe,
              const float* __restrict__ Wh1, const float* __restrict__ We1,
              const float* __restrict__ Wh2, const float* __restrict__ We2)
{
    int p = blockIdx.x * 256 + threadIdx.x;
    if (p >= TOTW / 2) return;
    const float* W;
    int Kd, Nd, local, base;
    if (p < 49152) {
        int m = p >> 13;
        local = p & 8191;
        Kd = 128; Nd = 128; base = m << 14;
        W = (m == 0) ? WQ : (m == 1) ? WK : (m == 2) ? WV :
            (m == 3) ? WE : (m == 4) ? WOh : WOe;
    } else if (p < 65536)  { local = p - 49152; Kd = 128; Nd = 256; base = OFF_WH1; W = Wh1; }
    else if (p < 81920)    { local = p - 65536; Kd = 128; Nd = 256; base = OFF_WE1; W = We1; }
    else if (p < 98304)    { local = p - 81920; Kd = 256; Nd = 128; base = OFF_WH2; W = Wh2; }
    else                   { local = p - 98304; Kd = 256; Nd = 128; base = OFF_WE2; W = We2; }
    int n  = local % Nd;
    int k  = (local / Nd) * 2;
    float x0 = W[(size_t)k * Nd + n];
    float x1 = W[(size_t)(k + 1) * Nd + n];
    uint32_t hi, lo;
    split_pair(x0, x1, hi, lo);
    size_t o = (size_t)base + (size_t)n * Kd + k;
    *(uint32_t*)((char*)g_Wb + o * 2)          = hi;
    *(uint32_t*)((char*)g_Wb + (o + TOTW) * 2) = lo;
}

// ============================================================================
// Pipelined HMMA bf16 3-split GEMM. K = 128, N = 128.
// C = [res +] (A(/Zrow)) @ W + bias; optional fused BN column stats.
// ============================================================================
#define A_CH_B 10240
#define A_BUF_B 20480
#define B_BASE 40960

__global__ __launch_bounds__(256, 2)
void k_mmgemm(const float* __restrict__ A, int Ald,
              const __nv_bfloat16* __restrict__ Whi,
              const __nv_bfloat16* __restrict__ Wlo,
              const float* __restrict__ bias, const float* __restrict__ res,
              float* __restrict__ C, int Cld, int M,
              const float* __restrict__ Zrow,
              double* sumP, double* sqP)
{
    extern __shared__ char smem[];
    constexpr int BS = 136;
    constexpr uint32_t BBs = 128u * BS * 2u;
    const uint32_t sbase = smem_u32(smem);

    const int tid  = threadIdx.x;
    const int lane = tid & 31;
    const int wid  = tid >> 5;
    const int wm   = wid >> 2;
    const int wn   = wid & 3;

    for (int i = tid; i < 128 * 16; i += 256) {
        int k8 = i & 15;
        int n  = i >> 4;
        uint4 vh = *(const uint4*)(Whi + (size_t)n * 128 + (k8 << 3));
        uint4 vl = *(const uint4*)(Wlo + (size_t)n * 128 + (k8 << 3));
        uint32_t off = ((uint32_t)n * BS + (k8 << 3)) * 2u;
        *(uint4*)(smem + B_BASE + off)       = vh;
        *(uint4*)(smem + B_BASE + BBs + off) = vl;
    }

    const int tiles = (M + 127) >> 7;
    const int a_row = (lane & 15);
    const int a_k   = (lane >> 4) << 3;
    const int b_row = (lane & 7) + ((lane >> 4) << 3);
    const int b_k   = ((lane >> 3) & 1) << 3;

    float4 pf[4];
    int t = blockIdx.x;
    if (t < tiles) {
        int m0 = t << 7;
        #pragma unroll
        for (int j = 0; j < 4; j++) {
            int idx = tid + (j << 8);
            int gm = m0 + (idx >> 3); if (gm > M - 1) gm = M - 1;
            pf[j] = *(const float4*)(A + (size_t)gm * Ald + ((idx & 7) << 2));
        }
    }
    int buf = 0;

    for (; t < tiles; t += gridDim.x) {
        const int m0 = t << 7;
        float acc[4][4][4] = {};
        for (int kc = 0; kc < 4; kc++) {
            const int kb = kc << 5;
            {
                char* ah_base = smem + buf * A_BUF_B;
                #pragma unroll
                for (int j = 0; j < 4; j++) {
                    int idx = tid + (j << 8);
                    int row = idx >> 3;
                    int c4  = (idx & 7) << 2;
                    float4 v = pf[j];
                    if (Zrow) {
                        int gm = m0 + row; if (gm > M - 1) gm = M - 1;
                        float zz = 1.0f / (Zrow[(size_t)gm * 8 + ((kb + c4) >> 4)] + 1e-6f);
                        v.x *= zz; v.y *= zz; v.z *= zz; v.w *= zz;
                    }
                    uint32_t h01, l01, h23, l23;
                    split_pair(v.x, v.y, h01, l01);
                    split_pair(v.z, v.w, h23, l23);
                    uint32_t off = ((uint32_t)row * 40 + c4) * 2u;
                    *(uint2*)(ah_base + off)          = make_uint2(h01, h23);
                    *(uint2*)(ah_base + A_CH_B + off) = make_uint2(l01, l23);
                }
            }
            __syncthreads();
            {
                int kc2 = kc + 1, tn = t;
                if (kc2 == 4) { kc2 = 0; tn = t + gridDim.x; }
                if (tn < tiles) {
                    int m2 = tn << 7, kb2 = kc2 << 5;
                    #pragma unroll
                    for (int j = 0; j < 4; j++) {
                        int idx = tid + (j << 8);
                        int gm = m2 + (idx >> 3); if (gm > M - 1) gm = M - 1;
                        pf[j] = *(const float4*)(A + (size_t)gm * Ald + kb2 + ((idx & 7) << 2));
                    }
                }
            }
            const uint32_t abase = sbase + buf * A_BUF_B;
            #pragma unroll
            for (int ks = 0; ks < 2; ks++) {
                const int ka = ks << 4;
                uint32_t bh[4][2], bl[4][2];
                #pragma unroll
                for (int np = 0; np < 2; np++) {
                    uint32_t roff = ((uint32_t)(wn * 32 + np * 16 + b_row) * BS
                                     + kb + ka + b_k) * 2u;
                    uint32_t rh[4], rl[4];
                    ldsm_x4(sbase + B_BASE + roff, rh);
                    ldsm_x4(sbase + B_BASE + BBs + roff, rl);
                    bh[np*2][0] = rh[0]; bh[np*2][1] = rh[1];
                    bh[np*2+1][0] = rh[2]; bh[np*2+1][1] = rh[3];
                    bl[np*2][0] = rl[0]; bl[np*2][1] = rl[1];
                    bl[np*2+1][0] = rl[2]; bl[np*2+1][1] = rl[3];
                }
                uint32_t ah[4][4], al[4][4];
                #pragma unroll
                for (int mt = 0; mt < 4; mt++) {
                    uint32_t roff = ((uint32_t)(wm * 64 + mt * 16 + a_row) * 40
                                     + ka + a_k) * 2u;
                    ldsm_x4(abase + roff, ah[mt]);
                    ldsm_x4(abase + A_CH_B + roff, al[mt]);
                }
                #pragma unroll
                for (int mt = 0; mt < 4; mt++)
                    #pragma unroll
                    for (int nt = 0; nt < 4; nt++) {
                        mma_bf16(acc[mt][nt], ah[mt], bh[nt]);
                        mma_bf16(acc[mt][nt], ah[mt], bl[nt]);
                        mma_bf16(acc[mt][nt], al[mt], bh[nt]);
                    }
            }
            buf ^= 1;
        }

        const int g  = lane >> 2;
        const int t2 = (lane & 3) << 1;
        #pragma unroll
        for (int nt = 0; nt < 4; nt++) {
            int c0 = wn * 32 + nt * 8 + t2;
            float2 bv = *(const float2*)(bias + c0);
            float ps0 = 0.f, ps1 = 0.f, q0 = 0.f, q1 = 0.f;
            #pragma unroll
            for (int mt = 0; mt < 4; mt++) {
                #pragma unroll
                for (int half = 0; half < 2; half++) {
                    int r = m0 + wm * 64 + mt * 16 + g + half * 8;
                    float2 v = make_float2(acc[mt][nt][half*2]   + bv.x,
                                           acc[mt][nt][half*2+1] + bv.y);
                    if (r < M) {
                        size_t o = (size_t)r * Cld + c0;
                        if (res) {
                            float2 rv = *(const float2*)(res + o);
                            v.x += rv.x; v.y += rv.y;
                        }
                        *(float2*)(C + o) = v;
                    } else { v.x = 0.f; v.y = 0.f; }
                    ps0 += v.x; q0 += v.x * v.x;
                    ps1 += v.y; q1 += v.y * v.y;
                }
            }
            if (sumP) {
                #pragma unroll
                for (int off = 16; off >= 4; off >>= 1) {
                    ps0 += __shfl_down_sync(0xffffffffu, ps0, off);
                    ps1 += __shfl_down_sync(0xffffffffu, ps1, off);
                    q0  += __shfl_down_sync(0xffffffffu, q0,  off);
                    q1  += __shfl_down_sync(0xffffffffu, q1,  off);
                }
                if (lane < 4) {
                    int cc = wn * 32 + nt * 8 + lane * 2;
                    atomicAdd(&sumP[cc],     (double)ps0);
                    atomicAdd(&sumP[cc + 1], (double)ps1);
                    atomicAdd(&sqP[cc],      (double)q0);
                    atomicAdd(&sqP[cc + 1],  (double)q1);
                }
            }
        }
    }
}

// ============================================================================
// Generic smem-GEMM step: acc += A(136-row smem, hi/lo) @ W(136-row smem, hi/lo)
// ============================================================================
__device__ __forceinline__ void ff_gemm(uint32_t sbase, uint32_t aHi, uint32_t aLo,
                                        uint32_t wHi, uint32_t wLo,
                                        int lane, int wm, int wn, float acc[4][4][4])
{
    const int a_row = (lane & 15);
    const int a_k   = (lane >> 4) << 3;
    const int b_row = (lane & 7) + ((lane >> 4) << 3);
    const int b_k   = ((lane >> 3) & 1) << 3;
    #pragma unroll
    for (int ks = 0; ks < 8; ks++) {
        const int ka = ks << 4;
        uint32_t bh[4][2], bl[4][2];
        #pragma unroll
        for (int np = 0; np < 2; np++) {
            uint32_t roff = ((uint32_t)(wn * 32 + np * 16 + b_row) * 136 + ka + b_k) * 2u;
            uint32_t rh[4], rl[4];
            ldsm_x4(sbase + wHi + roff, rh);
            ldsm_x4(sbase + wLo + roff, rl);
            bh[np*2][0] = rh[0]; bh[np*2][1] = rh[1];
            bh[np*2+1][0] = rh[2]; bh[np*2+1][1] = rh[3];
            bl[np*2][0] = rl[0]; bl[np*2][1] = rl[1];
            bl[np*2+1][0] = rl[2]; bl[np*2+1][1] = rl[3];
        }
        uint32_t ah[4][4], al[4][4];
        #pragma unroll
        for (int mt = 0; mt < 4; mt++) {
            uint32_t roff = ((uint32_t)(wm * 64 + mt * 16 + a_row) * 136 + ka + a_k) * 2u;
            ldsm_x4(sbase + aHi + roff, ah[mt]);
            ldsm_x4(sbase + aLo + roff, al[mt]);
        }
        #pragma unroll
        for (int mt = 0; mt < 4; mt++)
            #pragma unroll
            for (int nt = 0; nt < 4; nt++) {
                mma_bf16(acc[mt][nt], ah[mt], bh[nt]);
                mma_bf16(acc[mt][nt], ah[mt], bl[nt]);
                mma_bf16(acc[mt][nt], al[mt], bh[nt]);
            }
    }
}

// ============================================================================
// Fused QKV projections: one read of h; A tile resident; Q,K,V weights
// streamed through one smem W slot (L2-hot). smem total 139264 B.
// ============================================================================
#define QV_A_HI 0
#define QV_A_LO 34816
#define QV_W_HI 69632
#define QV_W_LO 104448

__global__ __launch_bounds__(256, 1)
void k_qkv(const float* __restrict__ A, int M,
           const __nv_bfloat16* __restrict__ Wq,
           const __nv_bfloat16* __restrict__ Wk,
           const __nv_bfloat16* __restrict__ Wv,
           const float* __restrict__ bq, const float* __restrict__ bk,
           const float* __restrict__ bv,
           float* __restrict__ Cq, float* __restrict__ Ck, float* __restrict__ Cv)
{
    extern __shared__ char smem[];
    const uint32_t sbase = smem_u32(smem);
    const int tid  = threadIdx.x;
    const int lane = tid & 31;
    const int wid  = tid >> 5;
    const int wm   = wid >> 2;
    const int wn   = wid & 3;
    const int g    = lane >> 2;
    const int t2   = (lane & 3) << 1;
    const int tiles = (M + 127) >> 7;

    const __nv_bfloat16* Ws[3] = {Wq, Wk, Wv};
    const float* bs[3] = {bq, bk, bv};
    float* Cs[3] = {Cq, Ck, Cv};

    for (int t = blockIdx.x; t < tiles; t += gridDim.x) {
        const int m0 = t << 7;
        __syncthreads();
        // stage A tile (split)
        for (int j = 0; j < 16; j++) {
            int idx = tid + (j << 8);
            int row = idx >> 5;
            int c4  = (idx & 31) << 2;
            int gm = m0 + row; if (gm > M - 1) gm = M - 1;
            float4 v = *(const float4*)(A + (size_t)gm * 128 + c4);
            uint32_t h01, l01, h23, l23;
            split_pair(v.x, v.y, h01, l01);
            split_pair(v.z, v.w, h23, l23);
            uint32_t off = ((uint32_t)row * 136 + c4) * 2u;
            *(uint2*)(smem + QV_A_HI + off) = make_uint2(h01, h23);
            *(uint2*)(smem + QV_A_LO + off) = make_uint2(l01, l23);
        }
        for (int w = 0; w < 3; w++) {
            // load W slot
            for (int i = tid; i < 2048; i += 256) {
                int n = i >> 4, k8 = i & 15;
                uint4 vh = *(const uint4*)(Ws[w] + (size_t)n * 128 + (k8 << 3));
                uint4 vl = *(const uint4*)(Ws[w] + TOTW + (size_t)n * 128 + (k8 << 3));
                uint32_t off = ((uint32_t)n * 136 + (k8 << 3)) * 2u;
                *(uint4*)(smem + QV_W_HI + off) = vh;
                *(uint4*)(smem + QV_W_LO + off) = vl;
            }
            __syncthreads();
            float acc[4][4][4] = {};
            ff_gemm(sbase, QV_A_HI, QV_A_LO, QV_W_HI, QV_W_LO, lane, wm, wn, acc);
            // epilogue
            float* C = Cs[w];
            const float* bias = bs[w];
            #pragma unroll
            for (int mt = 0; mt < 4; mt++) {
                int r0 = m0 + wm * 64 + mt * 16 + g;
                #pragma unroll
                for (int nt = 0; nt < 4; nt++) {
                    int c0 = wn * 32 + nt * 8 + t2;
                    float2 bvv = *(const float2*)(bias + c0);
                    #pragma unroll
                    for (int half = 0; half < 2; half++) {
                        int r = r0 + half * 8;
                        if (r >= M) continue;
                        *(float2*)(C + (size_t)r * 128 + c0) =
                            make_float2(acc[mt][nt][half*2]   + bvv.x,
                                        acc[mt][nt][half*2+1] + bvv.y);
                    }
                }
            }
            __syncthreads();   // W slot free for next weight
        }
    }
}

// ============================================================================
// Fused FFN: out = bn1(x) + relu(bn1(x)@W1 + b1)@W2 + b2, BN2 stats fused.
// ============================================================================
#define FF_A_HI 0
#define FF_A_LO 34816
#define FF_H_HI 69632
#define FF_H_LO 104448
#define FF_W_HI 139264
#define FF_W_LO 174080

__global__ __launch_bounds__(256, 1)
void k_ffnfused(const float* __restrict__ A, int M,
                const __nv_bfloat16* __restrict__ W1hi,
                const __nv_bfloat16* __restrict__ W1lo,
                const float* __restrict__ b1,
                const __nv_bfloat16* __restrict__ W2hi,
                const __nv_bfloat16* __restrict__ W2lo,
                const float* __restrict__ b2,
                float* __restrict__ C,
                const float* __restrict__ Asc, const float* __restrict__ Ash,
                double* sumP, double* sqP)
{
    extern __shared__ char smem[];
    const uint32_t sbase = smem_u32(smem);
    const int tid  = threadIdx.x;
    const int lane = tid & 31;
    const int wid  = tid >> 5;
    const int wm   = wid >> 2;
    const int wn   = wid & 3;
    const int g    = lane >> 2;
    const int t2   = (lane & 3) << 1;
    const int tiles = (M + 127) >> 7;

    for (int t = blockIdx.x; t < tiles; t += gridDim.x) {
        const int m0 = t << 7;
        __syncthreads();

        for (int j = 0; j < 16; j++) {
            int idx = tid + (j << 8);
            int row = idx >> 5;
            int c4  = (idx & 31) << 2;
            int gm = m0 + row; if (gm > M - 1) gm = M - 1;
            float4 v = *(const float4*)(A + (size_t)gm * 128 + c4);
            float4 sc = *(const float4*)(Asc + c4);
            float4 sh = *(const float4*)(Ash + c4);
            v.x = v.x * sc.x + sh.x;
            v.y = v.y * sc.y + sh.y;
            v.z = v.z * sc.z + sh.z;
            v.w = v.w * sc.w + sh.w;
            uint32_t h01, l01, h23, l23;
            split_pair(v.x, v.y, h01, l01);
            split_pair(v.z, v.w, h23, l23);
            uint32_t off = ((uint32_t)row * 136 + c4) * 2u;
            *(uint2*)(smem + FF_A_HI + off) = make_uint2(h01, h23);
            *(uint2*)(smem + FF_A_LO + off) = make_uint2(l01, l23);
        }
        for (int i = tid; i < 2048; i += 256) {
            int n = i >> 4, k8 = i & 15;
            uint4 vh = *(const uint4*)(W1hi + (size_t)n * 128 + (k8 << 3));
            uint4 vl = *(const uint4*)(W1lo + (size_t)n * 128 + (k8 << 3));
            uint32_t off = ((uint32_t)n * 136 + (k8 << 3)) * 2u;
            *(uint4*)(smem + FF_W_HI + off) = vh;
            *(uint4*)(smem + FF_W_LO + off) = vl;
        }
        __syncthreads();

        float acc2[4][4][4] = {};
        #pragma unroll
        for (int nh = 0; nh < 2; nh++) {
            float acc1[4][4][4] = {};
            ff_gemm(sbase, FF_A_HI, FF_A_LO, FF_W_HI, FF_W_LO, lane, wm, wn, acc1);
            __syncthreads();
            #pragma unroll
            for (int mt = 0; mt < 4; mt++) {
                #pragma unroll
                for (int nt = 0; nt < 4; nt++) {
                    int c = wn * 32 + nt * 8 + t2;
                    float2 bv = *(const float2*)(b1 + nh * 128 + c);
                    #pragma unroll
                    for (int half = 0; half < 2; half++) {
                        int rloc = wm * 64 + mt * 16 + g + half * 8;
                        float v0 = fmaxf(acc1[mt][nt][half*2]   + bv.x, 0.f);
                        float v1 = fmaxf(acc1[mt][nt][half*2+1] + bv.y, 0.f);
                        uint32_t hi, lo;
                        split_pair(v0, v1, hi, lo);
                        uint32_t off = ((uint32_t)rloc * 136 + c) * 2u;
                        *(uint32_t*)(smem + FF_H_HI + off) = hi;
                        *(uint32_t*)(smem + FF_H_LO + off) = lo;
                    }
                }
            }
            for (int i = tid; i < 2048; i += 256) {
                int n = i >> 4, k8 = i & 15;
                uint4 vh = *(const uint4*)(W2hi + (size_t)n * 256 + nh * 128 + (k8 << 3));
                uint4 vl = *(const uint4*)(W2lo + (size_t)n * 256 + nh * 128 + (k8 << 3));
                uint32_t off = ((uint32_t)n * 136 + (k8 << 3)) * 2u;
                *(uint4*)(smem + FF_W_HI + off) = vh;
                *(uint4*)(smem + FF_W_LO + off) = vl;
            }
            __syncthreads();
            ff_gemm(sbase, FF_H_HI, FF_H_LO, FF_W_HI, FF_W_LO, lane, wm, wn, acc2);
            if (nh == 0) {
                __syncthreads();
                for (int i = tid; i < 2048; i += 256) {
                    int n = i >> 4, k8 = i & 15;
                    uint4 vh = *(const uint4*)(W1hi + (size_t)(128 + n) * 128 + (k8 << 3));
                    uint4 vl = *(const uint4*)(W1lo + (size_t)(128 + n) * 128 + (k8 << 3));
                    uint32_t off = ((uint32_t)n * 136 + (k8 << 3)) * 2u;
                    *(uint4*)(smem + FF_W_HI + off) = vh;
                    *(uint4*)(smem + FF_W_LO + off) = vl;
                }
                __syncthreads();
            }
        }

        #pragma unroll
        for (int nt = 0; nt < 4; nt++) {
            int c0 = wn * 32 + nt * 8 + t2;
            float2 bv = *(const float2*)(b2 + c0);
            float ps0 = 0.f, ps1 = 0.f, q0 = 0.f, q1 = 0.f;
            #pragma unroll
            for (int mt = 0; mt < 4; mt++) {
                #pragma unroll
                for (int half = 0; half < 2; half++) {
                    int rloc = wm * 64 + mt * 16 + g + half * 8;
                    int r = m0 + rloc;
                    uint32_t off = ((uint32_t)rloc * 136 + c0) * 2u;
                    __nv_bfloat162 rh = *(__nv_bfloat162*)(smem + FF_A_HI + off);
                    __nv_bfloat162 rl = *(__nv_bfloat162*)(smem + FF_A_LO + off);
                    float2 v;
                    v.x = acc2[mt][nt][half*2]   + bv.x
                        + __bfloat162float(__low2bfloat16(rh))
                        + __bfloat162float(__low2bfloat16(rl));
                    v.y = acc2[mt][nt][half*2+1] + bv.y
                        + __bfloat162float(__high2bfloat16(rh))
                        + __bfloat162float(__high2bfloat16(rl));
                    if (r < M) {
                        *(float2*)(C + (size_t)r * 128 + c0) = v;
                    } else { v.x = 0.f; v.y = 0.f; }
                    ps0 += v.x; q0 += v.x * v.x;
                    ps1 += v.y; q1 += v.y * v.y;
                }
            }
            #pragma unroll
            for (int off = 16; off >= 4; off >>= 1) {
                ps0 += __shfl_down_sync(0xffffffffu, ps0, off);
                ps1 += __shfl_down_sync(0xffffffffu, ps1, off);
                q0  += __shfl_down_sync(0xffffffffu, q0,  off);
                q1  += __shfl_down_sync(0xffffffffu, q1,  off);
            }
            if (lane < 4) {
                int cc = wn * 32 + nt * 8 + lane * 2;
                atomicAdd(&sumP[cc],     (double)ps0);
                atomicAdd(&sumP[cc + 1], (double)ps1);
                atomicAdd(&sqP[cc],      (double)q0);
                atomicAdd(&sqP[cc + 1],  (double)q1);
            }
        }
    }
}

// ---------------- edge kernel: 1 warp = 2 edges, float4 vector atomics ------
__global__ __launch_bounds__(256)
void k_edge(const int* __restrict__ src, const int* __restrict__ dst)
{
    const int lane = threadIdx.x & 31;
    const int e0 = (blockIdx.x * 8 + (threadIdx.x >> 5)) * 2;
    const int c4 = lane << 2;           // column base 0..124
    int s0 = src[e0], d0 = dst[e0];
    int s1 = src[e0 + 1], d1 = dst[e0 + 1];
    float4 kv0 = *(const float4*)(g_K + (size_t)s0 * 128 + c4);
    float4 qv0 = *(const float4*)(g_Q + (size_t)d0 * 128 + c4);
    float4 ev0 = *(const float4*)(g_EA + (size_t)e0 * 128 + c4);
    float4 vv0 = *(const float4*)(g_V + (size_t)s0 * 128 + c4);
    float4 kv1 = *(const float4*)(g_K + (size_t)s1 * 128 + c4);
    float4 qv1 = *(const float4*)(g_Q + (size_t)d1 * 128 + c4);
    float4 ev1 = *(const float4*)(g_EA + (size_t)(e0 + 1) * 128 + c4);
    float4 vv1 = *(const float4*)(g_V + (size_t)s1 * 128 + c4);

    #pragma unroll
    for (int i = 0; i < 2; i++) {
        float4 kv = i ? kv1 : kv0;
        float4 qv = i ? qv1 : qv0;
        float4 ev = i ? ev1 : ev0;
        float4 vv = i ? vv1 : vv0;
        int d = i ? d1 : d0;
        float4 sc;
        sc.x = kv.x * qv.x * 0.25f * ev.x;
        sc.y = kv.y * qv.y * 0.25f * ev.y;
        sc.z = kv.z * qv.z * 0.25f * ev.z;
        sc.w = kv.w * qv.w * 0.25f * ev.w;
        *(float4*)(g_EA + (size_t)(e0 + i) * 128 + c4) = sc;
        float sum = sc.x + sc.y + sc.z + sc.w;
        sum += __shfl_xor_sync(0xffffffffu, sum, 1);
        sum += __shfl_xor_sync(0xffffffffu, sum, 2);
        sum = fminf(fmaxf(sum, -5.f), 5.f);
        float ss = __expf(sum);
        float4 add = make_float4(vv.x * ss, vv.y * ss, vv.z * ss, vv.w * ss);
        atomicAdd((float4*)(g_wV + (size_t)d * 128 + c4), add);
        if ((lane & 3) == 0)
            atomicAdd(&g_z[(size_t)d * 8 + (lane >> 2)], ss);
    }
}

// ---------------- batch-norm finalize / apply --------------------------------
__global__ void k_bn_finalize(int slot, float Mf,
                              const float* __restrict__ g, const float* __restrict__ b)
{
    int c = threadIdx.x;
    double mu  = g_sum[slot * 128 + c] / (double)Mf;
    double var = g_sq [slot * 128 + c] / (double)Mf - mu * mu;
    float sc = g[c] * rsqrtf((float)var + 1e-5f);
    g_bnsc[slot * 128 + c] = sc;
    g_bnsh[slot * 128 + c] = b[c] - (float)mu * sc;
}

__global__ __launch_bounds__(256)
void k_bn_apply(float* __restrict__ X, size_t M, int slot)
{
    size_t total4 = M * 32;
    size_t i = (size_t)blockIdx.x * blockDim.x + threadIdx.x;
    size_t stride = (size_t)gridDim.x * blockDim.x;
    for (size_t j = i; j < total4; j += stride) {
        int c = (int)(j & 31) * 4;
        const float* sc = g_bnsc + slot * 128 + c;
        const float* sh = g_bnsh + slot * 128 + c;
        float4 v = ((float4*)X)[j];
        v.x = v.x * sc[0] + sh[0];
        v.y = v.y * sc[1] + sh[1];
        v.z = v.z * sc[2] + sh[2];
        v.w = v.w * sc[3] + sh[3];
        ((float4*)X)[j] = v;
    }
}

// ---------------- host orchestration ---------------------------------------
static __nv_bfloat16* wb_base = nullptr;

static void mm4(const float* A, int woff,
                const float* bias, const float* res, float* C,
                int M,
                const float* Zrow = nullptr,
                double* sumP = nullptr, double* sqP = nullptr)
{
    int tiles = (M + 127) / 128;
    int grid = tiles < 296 ? tiles : 296;
    k_mmgemm<<<grid, 256, 110592>>>(A, 128, wb_base + woff, wb_base + woff + TOTW,
                                    bias, res, C, 128, M, Zrow, sumP, sqP);
}

extern "C" void kernel_launch(void* const* d_in, const int* in_sizes, int n_in,
                              void* d_out, int out_size)
{
    const float* h   = (const float*)d_in[0];
    const float* e   = (const float*)d_in[1];
    const int*   src = (const int*)d_in[2];
    const int*   dst = (const int*)d_in[3];
    const float* WQ  = (const float*)d_in[4];   const float* bQ  = (const float*)d_in[5];
    const float* WK  = (const float*)d_in[6];   const float* bK  = (const float*)d_in[7];
    const float* WV  = (const float*)d_in[8];   const float* bV  = (const float*)d_in[9];
    const float* WE  = (const float*)d_in[10];  const float* bE  = (const float*)d_in[11];
    const float* WOh = (const float*)d_in[12];  const float* bOh = (const float*)d_in[13];
    const float* WOe = (const float*)d_in[14];  const float* bOe = (const float*)d_in[15];
    const float* Wh1 = (const float*)d_in[16];  const float* bh1 = (const float*)d_in[17];
    const float* Wh2 = (const float*)d_in[18];  const float* bh2 = (const float*)d_in[19];
    const float* We1 = (const float*)d_in[20];  const float* be1 = (const float*)d_in[21];
    const float* We2 = (const float*)d_in[22];  const float* be2 = (const float*)d_in[23];
    const float* g1h = (const float*)d_in[24];
    const float* g1e = (const float*)d_in[25];
    const float* g2h = (const float*)d_in[26];
    const float* g2e = (const float*)d_in[27];
    const float* b1h = (const float*)d_in[28];
    const float* b1e = (const float*)d_in[29];
    const float* b2h = (const float*)d_in[30];
    const float* b2e = (const float*)d_in[31];

    float *pQ, *pK, *pV, *ph1, *pEA, *pe1, *pbnsc, *pbnsh, *pwV, *pz;
    double *psum, *psq;
    cudaGetSymbolAddress((void**)&pQ,    g_Q);
    cudaGetSymbolAddress((void**)&pK,    g_K);
    cudaGetSymbolAddress((void**)&pV,    g_V);
    cudaGetSymbolAddress((void**)&ph1,   g_h1);
    cudaGetSymbolAddress((void**)&pEA,   g_EA);
    cudaGetSymbolAddress((void**)&pe1,   g_e1);
    cudaGetSymbolAddress((void**)&pbnsc, g_bnsc);
    cudaGetSymbolAddress((void**)&pbnsh, g_bnsh);
    cudaGetSymbolAddress((void**)&pwV,   g_wV);
    cudaGetSymbolAddress((void**)&pz,    g_z);
    cudaGetSymbolAddress((void**)&psum,  g_sum);
    cudaGetSymbolAddress((void**)&psq,   g_sq);
    cudaGetSymbolAddress((void**)&wb_base, g_Wb);

    cudaFuncSetAttribute(k_mmgemm,   cudaFuncAttributeMaxDynamicSharedMemorySize, 110592);
    cudaFuncSetAttribute(k_qkv,      cudaFuncAttributeMaxDynamicSharedMemorySize, 139264);
    cudaFuncSetAttribute(k_ffnfused, cudaFuncAttributeMaxDynamicSharedMemorySize, 208896);

    float* out_h = (float*)d_out;
    float* out_e = (float*)d_out + (size_t)NN * 128;

    // 0) zero accumulators + BN stats; pre-split weights
    k_zero<<<4096, 256>>>();
    k_wsplit<<<448, 256>>>(WQ, WK, WV, WE, WOh, WOe, Wh1, We1, Wh2, We2);

    // 1) projections: fused QKV (reads h once) + E projection
    {
        int gh = (NN + 127) / 128; if (gh > 148) gh = 148;
        k_qkv<<<gh, 256, 139264>>>(h, NN,
            wb_base + OFF_WQ, wb_base + OFF_WK, wb_base + OFF_WV,
            bQ, bK, bV, pQ, pK, pV);
    }
    mm4(e, OFF_WE, bE, nullptr, pEA, EG);

    // 2) edge scores + attention weights + segment sums (float4 atomics)
    k_edge<<<EG / 16, 256>>>(src, dst);

    // 3+4) O projections; h_attn fused via Zrow; BN1 stats fused
    mm4(pwV, OFF_WOH, bOh, h, ph1, NN, pz, psum + 0,   psq + 0);
    mm4(pEA, OFF_WOE, bOe, e, pe1, EG, nullptr, psum + 128, psq + 128);

    // 5) BN #1 finalize
    k_bn_finalize<<<1, 128>>>(0, (float)NN, g1h, b1h);
    k_bn_finalize<<<1, 128>>>(1, (float)EG, g1e, b1e);

    // 6) fused FFNs
    {
        int gh = (NN + 127) / 128; if (gh > 148) gh = 148;
        k_ffnfused<<<gh, 256, 208896>>>(ph1, NN,
            wb_base + OFF_WH1, wb_base + OFF_WH1 + TOTW, bh1,
            wb_base + OFF_WH2, wb_base + OFF_WH2 + TOTW, bh2,
            out_h, pbnsc + 0, pbnsh + 0, psum + 256, psq + 256);
    }
    {
        int ge = (EG + 127) / 128; if (ge > 148) ge = 148;
        k_ffnfused<<<ge, 256, 208896>>>(pe1, EG,
            wb_base + OFF_WE1, wb_base + OFF_WE1 + TOTW, be1,
            wb_base + OFF_WE2, wb_base + OFF_WE2 + TOTW, be2,
            out_e, pbnsc + 128, pbnsh + 128, psum + 384, psq + 384);
    }

    // 7) BN #2 finalize + apply
    k_bn_finalize<<<1, 128>>>(2, (float)NN, g2h, b2h);
    k_bn_apply<<<12800, 256>>>(out_h, (size_t)NN, 2);
    k_bn_finalize<<<1, 128>>>(3, (float)EG, g2e, b2e);
    k_bn_apply<<<100000, 256>>>(out_e, (size_t)EG, 3);
}